// round 14
// baseline (speedup 1.0000x reference)
#include <cuda_runtime.h>
#include <cuda_bf16.h>
#include <cstdint>
#include <math.h>

#define T_LEN 1024
#define B_SZ  64
#define DH    256
#define NL    8
#define OUTL  24
#define M_TOT (B_SZ * T_LEN)
#define UP_T0_TILE 2

// ---------------- device scratch -------------------------------------------
__device__ __align__(128) float          g_h   [M_TOT * DH];
__device__ __align__(128) float          g_skip[M_TOT * DH];
__device__ __align__(128) __nv_bfloat16  g_hhi [M_TOT * DH];
__device__ __align__(128) __nv_bfloat16  g_hlo [M_TOT * DH];
__device__ __align__(128) __nv_bfloat16  g_ghi [M_TOT * DH];
__device__ __align__(128) __nv_bfloat16  g_glo [M_TOT * DH];
__device__ __align__(128) __nv_bfloat16  g_Wc_hi[NL * 3 * 512 * DH];
__device__ __align__(128) __nv_bfloat16  g_Wc_lo[NL * 3 * 512 * DH];
__device__ __align__(128) __nv_bfloat16  g_Ws_hi[NL * 512 * DH];
__device__ __align__(128) __nv_bfloat16  g_Ws_lo[NL * 512 * DH];
__device__ float g_loss;
// dependency flags
__device__ int g_cdone[NL * B_SZ * 8];
__device__ int g_sdone[NL * B_SZ * 8];
__device__ int g_udone[B_SZ * 8];
__device__ int g_wc[NL];
__device__ int g_ws[NL];

// layer-major schedule; CTA tile 128x128, 4 warps of 64x64
__constant__ int c_ts[NL]    = {3, 3, 3, 4, 4, 4, 5, 7};
__constant__ int c_convn[NL] = {1280, 1280, 1280, 1024, 1024, 1024, 768, 256}; // 4*nt*64
__constant__ int c_skipn[NL] = {768, 768, 768, 640, 640, 640, 512, 128};       // 2*(nt+1)*64; L7 skip-half only
#define N_PREP_C 1536
#define N_PREP_S 512
#define N_UP     384
#define FRONT    (N_PREP_C + N_PREP_S + N_UP)   // 2432
#define N_GEMM_CONV 7936
#define N_GEMM_SKIP 4864
#define MEGA_BLOCKS (FRONT + N_GEMM_CONV + N_GEMM_SKIP)  // 15232

// ---------------- PTX helpers ------------------------------------------------
__device__ __forceinline__ uint32_t cvta_s(const void* p) {
    uint32_t a;
    asm("{ .reg .u64 t; cvta.to.shared.u64 t, %1; cvt.u32.u64 %0, t; }" : "=r"(a) : "l"(p));
    return a;
}
__device__ __forceinline__ void ldsm4(uint32_t (&r)[4], uint32_t addr) {
    asm volatile("ldmatrix.sync.aligned.m8n8.x4.shared.b16 {%0,%1,%2,%3}, [%4];"
                 : "=r"(r[0]), "=r"(r[1]), "=r"(r[2]), "=r"(r[3]) : "r"(addr));
}
__device__ __forceinline__ void mma16816(float (&c)[4], const uint32_t (&a)[4],
                                         uint32_t b0, uint32_t b1) {
    asm volatile(
        "mma.sync.aligned.m16n8k16.row.col.f32.bf16.bf16.f32 "
        "{%0,%1,%2,%3}, {%4,%5,%6,%7}, {%8,%9}, {%0,%1,%2,%3};"
        : "+f"(c[0]), "+f"(c[1]), "+f"(c[2]), "+f"(c[3])
        : "r"(a[0]), "r"(a[1]), "r"(a[2]), "r"(a[3]), "r"(b0), "r"(b1));
}
__device__ __forceinline__ void cp16(uint32_t saddr, const void* g, bool pred) {
    int sz = pred ? 16 : 0;
    asm volatile("cp.async.cg.shared.global [%0], [%1], 16, %2;"
                 :: "r"(saddr), "l"(g), "r"(sz) : "memory");
}
#define CP_COMMIT() asm volatile("cp.async.commit_group;" ::: "memory")
#define CP_WAIT1()  asm volatile("cp.async.wait_group 1;" ::: "memory")
#define CP_WAIT0()  asm volatile("cp.async.wait_group 0;" ::: "memory")

__device__ __forceinline__ int ld_acq(const int* p) {
    int v;
    asm volatile("ld.acquire.gpu.global.b32 %0, [%1];" : "=r"(v) : "l"(p) : "memory");
    return v;
}
__device__ __forceinline__ void red_rel_add(int* p) {
    asm volatile("red.release.gpu.global.add.s32 [%0], 1;" :: "l"(p) : "memory");
}
__device__ __forceinline__ void spin_ge(const int* p, int tgt) {
    while (ld_acq(p) < tgt) __nanosleep(64);
}

// Stage: superplane A @0 (128 rows x 128B = [hi|lo], K=32), B @16KB (128 rows x 128B).
#define SP_B  16384
#define STG_SZ 32768
#define SMEM_DYN (3 * STG_SZ)     // 96KB; 2 CTA/SM
#define SWA(r, c) ((uint32_t)((r) * 128 + (((c) ^ ((r) & 7)) << 4)))

// ---------------- init: zero flags ------------------------------------------
__global__ void init_k() {
    int idx = blockIdx.x * blockDim.x + threadIdx.x;
    if (idx == 0) g_loss = 0.0f;
    if (idx < NL * B_SZ * 8) { g_cdone[idx] = 0; g_sdone[idx] = 0; }
    if (idx < B_SZ * 8) g_udone[idx] = 0;
    if (idx < NL) { g_wc[idx] = 0; g_ws[idx] = 0; }
}

// ---------------- mega kernel (128 threads) -----------------------------------
__global__ __launch_bounds__(128, 2) void mega(
    const float* __restrict__ conv_w, const float* __restrict__ skip_w,
    const float* __restrict__ X_lag,  const float* __restrict__ X_cov,
    const float* __restrict__ up_w,   const float* __restrict__ up_b,
    const float* __restrict__ conv_b, const float* __restrict__ skip_b) {
    extern __shared__ __align__(16) unsigned char sm[];
    const int tid = threadIdx.x;
    int id = blockIdx.x;

    // ===== front: weight prep + up projection =====
    if (id < N_PREP_C) {
        int layer = id / 192;
        int base = (id % 192) * 2048;
#pragma unroll
        for (int e = 0; e < 16; e++) {
            int loc = base + e * 128 + tid;
            int ic = loc & 255;
            int np = (loc >> 8) & 511;
            int tap = loc >> 17;
            int c = np >> 1, s = np & 1;
            int oc = c + s * 256;
            size_t gidx = (size_t)layer * (3 * 512 * 256) + loc;
            float v = conv_w[((size_t)(layer * 512 + oc) * DH + ic) * 3 + tap];
            __nv_bfloat16 hi = __float2bfloat16(v);
            g_Wc_hi[gidx] = hi;
            g_Wc_lo[gidx] = __float2bfloat16(v - __bfloat162float(hi));
        }
        __syncthreads();
        if (tid == 0) red_rel_add(&g_wc[layer]);
        return;
    }
    if (id < N_PREP_C + N_PREP_S) {
        id -= N_PREP_C;
        int layer = id / 64;
        int base = (id % 64) * 2048;
#pragma unroll
        for (int e = 0; e < 16; e++) {
            int loc = base + e * 128 + tid;
            size_t gidx = (size_t)layer * (512 * 256) + loc;
            float v = skip_w[gidx];
            __nv_bfloat16 hi = __float2bfloat16(v);
            g_Ws_hi[gidx] = hi;
            g_Ws_lo[gidx] = __float2bfloat16(v - __bfloat162float(hi));
        }
        __syncthreads();
        if (tid == 0) red_rel_add(&g_ws[layer]);
        return;
    }
    if (id < FRONT) {
        id -= N_PREP_C + N_PREP_S;
        int bidx = id / 6;
        int ttile = UP_T0_TILE + id % 6;
        int t0 = ttile * 128;
        float* xs = (float*)sm;   // [128][16]
#pragma unroll
        for (int i = 0; i < 16; i++) {
            int e = tid + i * 128;
            int r = e >> 4, j = e & 15;
            int t = t0 + r;
            xs[e] = (j < 8) ? X_lag[((size_t)t * B_SZ + bidx) * 8 + j]
                            : X_cov[((size_t)t * B_SZ + bidx) * 8 + (j - 8)];
        }
        __syncthreads();
        int c0 = tid, c1 = tid + 128;
        float w0[16], w1[16];
#pragma unroll
        for (int j = 0; j < 16; j++) { w0[j] = up_w[j * DH + c0]; w1[j] = up_w[j * DH + c1]; }
        float b0 = up_b[c0], b1 = up_b[c1];
        for (int r = 0; r < 128; r++) {
            float a0 = b0, a1 = b1;
            const float* xr = xs + r * 16;
#pragma unroll
            for (int j = 0; j < 16; j++) { a0 += xr[j] * w0[j]; a1 += xr[j] * w1[j]; }
            size_t o = ((size_t)bidx * T_LEN + t0 + r) * DH;
            g_h[o + c0] = a0;
            g_h[o + c1] = a1;
            __nv_bfloat16 h0 = __float2bfloat16(a0), h1 = __float2bfloat16(a1);
            g_hhi[o + c0] = h0;
            g_hhi[o + c1] = h1;
            g_hlo[o + c0] = __float2bfloat16(a0 - __bfloat162float(h0));
            g_hlo[o + c1] = __float2bfloat16(a1 - __bfloat162float(h1));
        }
        __syncthreads();
        if (tid == 0) red_rel_add(&g_udone[bidx * 8 + ttile]);
        return;
    }

    // ===== GEMM section: CTA 128x128, 4 warps of 64x64 =====
    int rem = id - FRONT;
    int layer = 0;
    while (layer < NL - 1 && rem >= c_convn[layer] + c_skipn[layer]) {
        rem -= c_convn[layer] + c_skipn[layer];
        layer++;
    }
    const int tstart = c_ts[layer];
    const int nt = 8 - tstart;
    const bool isconv = rem < c_convn[layer];

    const int wid = tid >> 5, lid = tid & 31;
    const int wm = wid & 1, wn = wid >> 1;          // 2x2 warps of 64x64
    const uint32_t smb = cvta_s(sm);
    const int lrow = lid & 15, khalf = lid >> 4;

    float acc[4][8][4];
#pragma unroll
    for (int a = 0; a < 4; a++)
#pragma unroll
        for (int b = 0; b < 8; b++)
#pragma unroll
            for (int d = 0; d < 4; d++) acc[a][b][d] = 0.0f;

    if (isconv) {
        const int nx = rem & 3;                     // 4 N-tiles of 128
        const int y = rem >> 2;
        const int bidx = y / nt;
        const int ttile = tstart + y % nt;
        const int n0 = nx * 128;
        const int m0 = bidx * T_LEN + ttile * 128;
        const int t0 = ttile * 128;
        const int dil = 1 << layer;

        if (tid == 0) {
            spin_ge(&g_wc[layer], 192);
            if (layer == 0) {
                spin_ge(&g_udone[bidx * 8 + ttile], 1);
                spin_ge(&g_udone[bidx * 8 + ttile - 1], 1);
            } else {
                int lo = ttile - 2, tsp = c_ts[layer - 1];
                if (lo < tsp) lo = tsp;
                for (int tp = lo; tp <= ttile; tp++) {
                    int tgt = (tp == 7) ? 4 : 2;
                    spin_ge(&g_sdone[((layer - 1) * B_SZ + bidx) * 8 + tp], tgt);
                }
            }
        }
        __syncthreads();

        const bool predA = true;  // per-row pred computed inside
        (void)predA;
        auto issue = [&](int it, uint32_t stgoff) {
            int tap = it >> 3, kc = it & 7;
            int kk = kc * 32;
            int off = (2 - tap) * dil;
            bool p = (t0 + tid) >= off;
            const __nv_bfloat16* Ah = g_hhi + ((long)(m0 - off + tid)) * DH + kk;
            const __nv_bfloat16* Al = g_hlo + ((long)(m0 - off + tid)) * DH + kk;
            const __nv_bfloat16* Bh = g_Wc_hi + ((size_t)(layer * 3 + tap) * 512 + n0 + tid) * DH + kk;
            const __nv_bfloat16* Bl = g_Wc_lo + ((size_t)(layer * 3 + tap) * 512 + n0 + tid) * DH + kk;
            uint32_t sb = smb + stgoff;
#pragma unroll
            for (int c = 0; c < 4; c++) {
                cp16(sb + SWA(tid, c),             Ah + c * 8, p);
                cp16(sb + SWA(tid, c + 4),         Al + c * 8, p);
                cp16(sb + SP_B + SWA(tid, c),      Bh + c * 8, true);
                cp16(sb + SP_B + SWA(tid, c + 4),  Bl + c * 8, true);
            }
            CP_COMMIT();
        };
        auto compute = [&](uint32_t s0) {
#pragma unroll
            for (int ks = 0; ks < 2; ks++) {
                int ch = 2 * ks + khalf;
                uint32_t ah[4][4], al[4][4], bH[4][4], bL[4][4];
#pragma unroll
                for (int q = 0; q < 4; q++) {
                    int rB = wn * 64 + q * 16 + lrow;
                    ldsm4(bH[q], s0 + SP_B + SWA(rB, ch));
                    ldsm4(bL[q], s0 + SP_B + SWA(rB, ch + 4));
                }
#pragma unroll
                for (int mt = 0; mt < 4; mt++)
                    ldsm4(ah[mt], s0 + SWA(wm * 64 + mt * 16 + lrow, ch));
#pragma unroll
                for (int mt = 0; mt < 4; mt++)
#pragma unroll
                    for (int q = 0; q < 4; q++)
#pragma unroll
                        for (int h = 0; h < 2; h++) {
                            mma16816(acc[mt][q * 2 + h], ah[mt], bH[q][h], bH[q][h + 2]);
                            mma16816(acc[mt][q * 2 + h], ah[mt], bL[q][h], bL[q][h + 2]);
                        }
#pragma unroll
                for (int mt = 0; mt < 4; mt++)
                    ldsm4(al[mt], s0 + SWA(wm * 64 + mt * 16 + lrow, ch + 4));
#pragma unroll
                for (int mt = 0; mt < 4; mt++)
#pragma unroll
                    for (int q = 0; q < 4; q++)
#pragma unroll
                        for (int h = 0; h < 2; h++)
                            mma16816(acc[mt][q * 2 + h], al[mt], bH[q][h], bH[q][h + 2]);
            }
        };

        issue(0, 0);
        issue(1, STG_SZ);
        for (int mj = 0; mj < 7; mj++) {
            CP_WAIT1(); __syncthreads(); issue(mj * 3 + 2, 2 * STG_SZ); compute(smb);
            CP_WAIT1(); __syncthreads(); issue(mj * 3 + 3, 0);          compute(smb + STG_SZ);
            CP_WAIT1(); __syncthreads(); issue(mj * 3 + 4, STG_SZ);     compute(smb + 2 * STG_SZ);
        }
        CP_WAIT1(); __syncthreads(); issue(23, 2 * STG_SZ); compute(smb);
        CP_WAIT1(); __syncthreads();                         compute(smb + STG_SZ);
        CP_WAIT0(); __syncthreads();                         compute(smb + 2 * STG_SZ);

        // epilogue: gated = tanh(f)*sigmoid(g)
        const float* cbf = conv_b + layer * 512;
        const int lm = lid >> 2, ln = lid & 3;
#pragma unroll
        for (int mt = 0; mt < 4; mt++) {
            int row0 = m0 + wm * 64 + mt * 16 + lm;
#pragma unroll
            for (int nn = 0; nn < 8; nn++) {
                int ch = ((n0 + wn * 64 + nn * 8) >> 1) + ln;
                float fb = __ldg(cbf + ch), gb = __ldg(cbf + 256 + ch);
#pragma unroll
                for (int u = 0; u < 2; u++) {
                    int row = row0 + u * 8;
                    float f = acc[mt][nn][2 * u] + fb;
                    float g = acc[mt][nn][2 * u + 1] + gb;
                    float e2f = __expf(2.0f * f);
                    float th = (e2f - 1.0f) / (e2f + 1.0f);
                    float val = th / (1.0f + __expf(-g));
                    __nv_bfloat16 hi = __float2bfloat16(val);
                    g_ghi[(size_t)row * DH + ch] = hi;
                    g_glo[(size_t)row * DH + ch] = __float2bfloat16(val - __bfloat162float(hi));
                }
            }
        }
        __syncthreads();
        if (tid == 0) red_rel_add(&g_cdone[(layer * B_SZ + bidx) * 8 + ttile]);
    } else {
        int s = rem - c_convn[layer];
        const int x = s & 1;                        // 2 N-tiles of 128 per half
        int jj, bb;
        if (layer == NL - 1) { bb = s >> 1; jj = nt; }
        else { bb = (s >> 1) / (nt + 1); jj = (s >> 1) % (nt + 1); }
        const int ttile = (jj < nt) ? (tstart + jj) : 7;
        const int n0 = ((jj < nt) ? 0 : 256) + x * 128;
        const int m0 = bb * T_LEN + ttile * 128;

        if (tid == 0) {
            spin_ge(&g_ws[layer], 64);
            int hi_t = ttile + 2;
            if (hi_t > 7) hi_t = 7;
            for (int tp = ttile; tp <= hi_t; tp++)
                spin_ge(&g_cdone[(layer * B_SZ + bb) * 8 + tp], 4);
        }
        __syncthreads();

        const __nv_bfloat16* Ah0 = g_ghi + (size_t)(m0 + tid) * DH;
        const __nv_bfloat16* Al0 = g_glo + (size_t)(m0 + tid) * DH;
        const __nv_bfloat16* Bh0 = g_Ws_hi + ((size_t)layer * 512 + n0 + tid) * DH;
        const __nv_bfloat16* Bl0 = g_Ws_lo + ((size_t)layer * 512 + n0 + tid) * DH;

        auto issue = [&](int it, uint32_t stgoff) {
            int kk = it * 32;
            uint32_t sb = smb + stgoff;
#pragma unroll
            for (int c = 0; c < 4; c++) {
                cp16(sb + SWA(tid, c),             Ah0 + kk + c * 8, true);
                cp16(sb + SWA(tid, c + 4),         Al0 + kk + c * 8, true);
                cp16(sb + SP_B + SWA(tid, c),      Bh0 + kk + c * 8, true);
                cp16(sb + SP_B + SWA(tid, c + 4),  Bl0 + kk + c * 8, true);
            }
            CP_COMMIT();
        };
        auto compute = [&](uint32_t s0) {
#pragma unroll
            for (int ks = 0; ks < 2; ks++) {
                int ch = 2 * ks + khalf;
                uint32_t ah[4][4], al[4][4], bH[4][4], bL[4][4];
#pragma unroll
                for (int q = 0; q < 4; q++) {
                    int rB = wn * 64 + q * 16 + lrow;
                    ldsm4(bH[q], s0 + SP_B + SWA(rB, ch));
                    ldsm4(bL[q], s0 + SP_B + SWA(rB, ch + 4));
                }
#pragma unroll
                for (int mt = 0; mt < 4; mt++)
                    ldsm4(ah[mt], s0 + SWA(wm * 64 + mt * 16 + lrow, ch));
#pragma unroll
                for (int mt = 0; mt < 4; mt++)
#pragma unroll
                    for (int q = 0; q < 4; q++)
#pragma unroll
                        for (int h = 0; h < 2; h++) {
                            mma16816(acc[mt][q * 2 + h], ah[mt], bH[q][h], bH[q][h + 2]);
                            mma16816(acc[mt][q * 2 + h], ah[mt], bL[q][h], bL[q][h + 2]);
                        }
#pragma unroll
                for (int mt = 0; mt < 4; mt++)
                    ldsm4(al[mt], s0 + SWA(wm * 64 + mt * 16 + lrow, ch + 4));
#pragma unroll
                for (int mt = 0; mt < 4; mt++)
#pragma unroll
                    for (int q = 0; q < 4; q++)
#pragma unroll
                        for (int h = 0; h < 2; h++)
                            mma16816(acc[mt][q * 2 + h], al[mt], bH[q][h], bH[q][h + 2]);
            }
        };

        issue(0, 0);
        issue(1, STG_SZ);
        CP_WAIT1(); __syncthreads(); issue(2, 2 * STG_SZ); compute(smb);
        CP_WAIT1(); __syncthreads(); issue(3, 0);          compute(smb + STG_SZ);
        CP_WAIT1(); __syncthreads(); issue(4, STG_SZ);     compute(smb + 2 * STG_SZ);
        CP_WAIT1(); __syncthreads(); issue(5, 2 * STG_SZ); compute(smb);
        CP_WAIT1(); __syncthreads(); issue(6, 0);          compute(smb + STG_SZ);
        CP_WAIT1(); __syncthreads(); issue(7, STG_SZ);     compute(smb + 2 * STG_SZ);
        CP_WAIT1(); __syncthreads();                       compute(smb);
        CP_WAIT0(); __syncthreads();                       compute(smb + STG_SZ);

        const float* sb_ = skip_b + layer * 512;
        const int lm = lid >> 2, ln = lid & 3;
        const bool is_h = (n0 < 256);
#pragma unroll
        for (int mt = 0; mt < 4; mt++) {
            int row0 = m0 + wm * 64 + mt * 16 + lm;
#pragma unroll
            for (int nn = 0; nn < 8; nn++) {
                int oc = n0 + wn * 64 + nn * 8 + 2 * ln;
                float b0 = __ldg(sb_ + oc), b1 = __ldg(sb_ + oc + 1);
#pragma unroll
                for (int u = 0; u < 2; u++) {
                    int row = row0 + u * 8;
                    float v0 = acc[mt][nn][2 * u] + b0;
                    float v1 = acc[mt][nn][2 * u + 1] + b1;
                    if (is_h) {
                        float2* hp = (float2*)(g_h + (size_t)row * DH + oc);
                        float2 cur = *hp;
                        float nh0 = cur.x + v0, nh1 = cur.y + v1;
                        *hp = make_float2(nh0, nh1);
                        __nv_bfloat16 a0 = __float2bfloat16(nh0);
                        __nv_bfloat16 a1 = __float2bfloat16(nh1);
                        *(__nv_bfloat162*)(g_hhi + (size_t)row * DH + oc) = __nv_bfloat162(a0, a1);
                        *(__nv_bfloat162*)(g_hlo + (size_t)row * DH + oc) = __nv_bfloat162(
                            __float2bfloat16(nh0 - __bfloat162float(a0)),
                            __float2bfloat16(nh1 - __bfloat162float(a1)));
                    } else {
                        float2* sp = (float2*)(g_skip + (size_t)row * DH + (oc - 256));
                        float2 prev = (layer == 0) ? make_float2(0.f, 0.f) : *sp;
                        *sp = make_float2(prev.x + v0, prev.y + v1);
                    }
                }
            }
        }
        __syncthreads();
        if (tid == 0) red_rel_add(&g_sdone[(layer * B_SZ + bb) * 8 + ttile]);
    }
}

// ---------------- FC head + Gaussian NLL ------------------------------------
__global__ __launch_bounds__(256) void final_k(
    const float* __restrict__ y,
    const float* __restrict__ fc_w, const float* __restrict__ fc_b,
    const float* __restrict__ loc_w, const float* __restrict__ loc_b,
    const float* __restrict__ scale_w, const float* __restrict__ scale_b,
    float* __restrict__ out) {
    int row = blockIdx.x;
    int tt = row >> 6;
    int b = row & 63;
    int t = T_LEN - OUTL + tt;
    size_t r = (size_t)b * T_LEN + t;
    __shared__ float srow[DH];
    __shared__ float red[256];
    int c = threadIdx.x;
    srow[c] = g_skip[r * DH + c];
    __syncthreads();
    float acc = fc_b[c];
#pragma unroll 8
    for (int k = 0; k < DH; k++) acc += srow[k] * fc_w[k * DH + c];
    float ff = fmaxf(acc, 0.0f);

    red[c] = ff * loc_w[c];
    __syncthreads();
    for (int s = 128; s > 0; s >>= 1) {
        if (c < s) red[c] += red[c + s];
        __syncthreads();
    }
    float loc = red[0] + loc_b[0];
    __syncthreads();

    red[c] = ff * scale_w[c];
    __syncthreads();
    for (int s = 128; s > 0; s >>= 1) {
        if (c < s) red[c] += red[c + s];
        __syncthreads();
    }
    if (c == 0) {
        float sraw = red[0] + scale_b[0];
        float sp = (sraw > 20.0f) ? sraw : log1pf(expf(sraw));
        float scale = sp + 1e-6f;
        float yt = y[(size_t)t * B_SZ + b];
        float z = (yt - loc) / scale;
        float lp = -0.5f * z * z - logf(scale) - 0.91893853320467274f;
        out[2 + row] = loc;
        out[2 + OUTL * B_SZ + row] = scale;
        atomicAdd(&g_loss, lp);
    }
}

__global__ void finish_k(float* __restrict__ out) {
    float L = -g_loss / (float)(OUTL * B_SZ);
    out[0] = L;
    out[1] = L;
}

// ---------------- launch -----------------------------------------------------
extern "C" void kernel_launch(void* const* d_in, const int* in_sizes, int n_in,
                              void* d_out, int out_size) {
    const float* X_cov   = (const float*)d_in[1];
    const float* X_lag   = (const float*)d_in[2];
    const float* y       = (const float*)d_in[3];
    const float* up_w    = (const float*)d_in[5];
    const float* up_b    = (const float*)d_in[6];
    const float* conv_w  = (const float*)d_in[7];
    const float* conv_b  = (const float*)d_in[8];
    const float* skip_w  = (const float*)d_in[9];
    const float* skip_b  = (const float*)d_in[10];
    const float* fc_w    = (const float*)d_in[11];
    const float* fc_b    = (const float*)d_in[12];
    const float* loc_w   = (const float*)d_in[13];
    const float* loc_b   = (const float*)d_in[14];
    const float* scale_w = (const float*)d_in[15];
    const float* scale_b = (const float*)d_in[16];
    float* out = (float*)d_out;

    cudaFuncSetAttribute(mega, cudaFuncAttributeMaxDynamicSharedMemorySize, SMEM_DYN);

    init_k<<<(NL * B_SZ * 8 + 255) / 256, 256>>>();
    mega<<<MEGA_BLOCKS, 128, SMEM_DYN>>>(conv_w, skip_w, X_lag, X_cov,
                                         up_w, up_b, conv_b, skip_b);
    final_k<<<OUTL * B_SZ, 256>>>(y, fc_w, fc_b, loc_w, loc_b, scale_w, scale_b, out);
    finish_k<<<1, 1>>>(out);
}

// round 15
// speedup vs baseline: 1.6949x; 1.6949x over previous
#include <cuda_runtime.h>
#include <cuda_bf16.h>
#include <cstdint>
#include <math.h>

#define T_LEN 1024
#define B_SZ  64
#define DH    256
#define NL    8
#define OUTL  24
#define M_TOT (B_SZ * T_LEN)
#define UP_T0_TILE 2              // up computed for t-tiles 2..7

// ---------------- device scratch -------------------------------------------
__device__ __align__(128) float          g_h   [M_TOT * DH];
__device__ __align__(128) float          g_skip[M_TOT * DH];
__device__ __align__(128) __nv_bfloat16  g_hhi [M_TOT * DH];
__device__ __align__(128) __nv_bfloat16  g_hlo [M_TOT * DH];
__device__ __align__(128) __nv_bfloat16  g_ghi [M_TOT * DH];
__device__ __align__(128) __nv_bfloat16  g_glo [M_TOT * DH];
__device__ __align__(128) __nv_bfloat16  g_Wc_hi[NL * 3 * 512 * DH];
__device__ __align__(128) __nv_bfloat16  g_Wc_lo[NL * 3 * 512 * DH];
__device__ __align__(128) __nv_bfloat16  g_Ws_hi[NL * 512 * DH];
__device__ __align__(128) __nv_bfloat16  g_Ws_lo[NL * 512 * DH];
__device__ float g_loss;
// dependency flags
__device__ int g_cdone[NL * B_SZ * 8];
__device__ int g_sdone[NL * B_SZ * 8];
__device__ int g_udone[B_SZ * 8];
__device__ int g_wc[NL];
__device__ int g_ws[NL];

// layer-major schedule, L7 skip h-half dropped
__constant__ int c_ts[NL]    = {3, 3, 3, 4, 4, 4, 5, 7};
__constant__ int c_convn[NL] = {2560, 2560, 2560, 2048, 2048, 2048, 1536, 512};
__constant__ int c_skipn[NL] = {1536, 1536, 1536, 1280, 1280, 1280, 1024, 256};
// front: conv-w prep 8*192, skip-w prep 8*64, up 64*6
#define N_PREP_C 1536
#define N_PREP_S 512
#define N_UP     384
#define FRONT    (N_PREP_C + N_PREP_S + N_UP)   // 2432
#define N_GEMM_CONV 15872                        // sum c_convn
#define N_GEMM_SKIP 9728                         // sum c_skipn
#define MEGA_BLOCKS (FRONT + N_GEMM_CONV + N_GEMM_SKIP)  // 28032

// ---------------- PTX helpers ------------------------------------------------
__device__ __forceinline__ uint32_t cvta_s(const void* p) {
    uint32_t a;
    asm("{ .reg .u64 t; cvta.to.shared.u64 t, %1; cvt.u32.u64 %0, t; }" : "=r"(a) : "l"(p));
    return a;
}
__device__ __forceinline__ void ldsm4(uint32_t (&r)[4], uint32_t addr) {
    asm volatile("ldmatrix.sync.aligned.m8n8.x4.shared.b16 {%0,%1,%2,%3}, [%4];"
                 : "=r"(r[0]), "=r"(r[1]), "=r"(r[2]), "=r"(r[3]) : "r"(addr));
}
__device__ __forceinline__ void mma16816(float (&c)[4], const uint32_t (&a)[4],
                                         uint32_t b0, uint32_t b1) {
    asm volatile(
        "mma.sync.aligned.m16n8k16.row.col.f32.bf16.bf16.f32 "
        "{%0,%1,%2,%3}, {%4,%5,%6,%7}, {%8,%9}, {%0,%1,%2,%3};"
        : "+f"(c[0]), "+f"(c[1]), "+f"(c[2]), "+f"(c[3])
        : "r"(a[0]), "r"(a[1]), "r"(a[2]), "r"(a[3]), "r"(b0), "r"(b1));
}
__device__ __forceinline__ void cp16(uint32_t saddr, const void* g, bool pred) {
    int sz = pred ? 16 : 0;
    asm volatile("cp.async.cg.shared.global [%0], [%1], 16, %2;"
                 :: "r"(saddr), "l"(g), "r"(sz) : "memory");
}
#define CP_COMMIT() asm volatile("cp.async.commit_group;" ::: "memory")
#define CP_WAIT1()  asm volatile("cp.async.wait_group 1;" ::: "memory")
#define CP_WAIT0()  asm volatile("cp.async.wait_group 0;" ::: "memory")

__device__ __forceinline__ int ld_acq(const int* p) {
    int v;
    asm volatile("ld.acquire.gpu.global.b32 %0, [%1];" : "=r"(v) : "l"(p) : "memory");
    return v;
}
__device__ __forceinline__ void red_rel_add(int* p) {
    asm volatile("red.release.gpu.global.add.s32 [%0], 1;" :: "l"(p) : "memory");
}
__device__ __forceinline__ void spin_ge(const int* p, int tgt) {
    while (ld_acq(p) < tgt) __nanosleep(64);
}

// Stage: superplane A @0 (128 rows x 128B = [hi|lo]), B @16KB (64 rows x 128B).
#define SP_B  16384
#define STG_SZ 24576
#define SMEM_DYN (3 * STG_SZ)
#define SWA(r, c) ((uint32_t)((r) * 128 + (((c) ^ ((r) & 7)) << 4)))

// ---------------- init: zero flags ------------------------------------------
__global__ void init_k() {
    int idx = blockIdx.x * blockDim.x + threadIdx.x;
    if (idx == 0) g_loss = 0.0f;
    if (idx < NL * B_SZ * 8) { g_cdone[idx] = 0; g_sdone[idx] = 0; }
    if (idx < B_SZ * 8) g_udone[idx] = 0;
    if (idx < NL) { g_wc[idx] = 0; g_ws[idx] = 0; }
}

// ---------------- mega kernel ------------------------------------------------
__global__ __launch_bounds__(256, 3) void mega(
    const float* __restrict__ conv_w, const float* __restrict__ skip_w,
    const float* __restrict__ X_lag,  const float* __restrict__ X_cov,
    const float* __restrict__ up_w,   const float* __restrict__ up_b,
    const float* __restrict__ conv_b, const float* __restrict__ skip_b) {
    extern __shared__ __align__(16) unsigned char sm[];
    const int tid = threadIdx.x;
    int id = blockIdx.x;

    // ===== front section: weight prep + up projection =====
    if (id < N_PREP_C) {
        int layer = id / 192;
        int base = (id % 192) * 2048;
#pragma unroll
        for (int e = 0; e < 8; e++) {
            int loc = base + tid * 8 + e;
            int ic = loc & 255;
            int np = (loc >> 8) & 511;
            int tap = loc >> 17;
            int c = np >> 1, s = np & 1;
            int oc = c + s * 256;
            size_t gidx = (size_t)layer * (3 * 512 * 256) + loc;
            float v = conv_w[((size_t)(layer * 512 + oc) * DH + ic) * 3 + tap];
            __nv_bfloat16 hi = __float2bfloat16(v);
            g_Wc_hi[gidx] = hi;
            g_Wc_lo[gidx] = __float2bfloat16(v - __bfloat162float(hi));
        }
        __syncthreads();
        if (tid == 0) red_rel_add(&g_wc[layer]);
        return;
    }
    if (id < N_PREP_C + N_PREP_S) {
        id -= N_PREP_C;
        int layer = id / 64;
        int base = (id % 64) * 2048;
#pragma unroll
        for (int e = 0; e < 8; e++) {
            int loc = base + tid * 8 + e;
            size_t gidx = (size_t)layer * (512 * 256) + loc;
            float v = skip_w[gidx];
            __nv_bfloat16 hi = __float2bfloat16(v);
            g_Ws_hi[gidx] = hi;
            g_Ws_lo[gidx] = __float2bfloat16(v - __bfloat162float(hi));
        }
        __syncthreads();
        if (tid == 0) red_rel_add(&g_ws[layer]);
        return;
    }
    if (id < FRONT) {
        id -= N_PREP_C + N_PREP_S;
        int bidx = id / 6;
        int ttile = UP_T0_TILE + id % 6;
        int t0 = ttile * 128;
        float* xs = (float*)sm;   // [128][16]
#pragma unroll
        for (int i = 0; i < 8; i++) {
            int e = tid + i * 256;
            int r = e >> 4, j = e & 15;
            int t = t0 + r;
            xs[e] = (j < 8) ? X_lag[((size_t)t * B_SZ + bidx) * 8 + j]
                            : X_cov[((size_t)t * B_SZ + bidx) * 8 + (j - 8)];
        }
        __syncthreads();
        int c = tid;
        float w[16];
#pragma unroll
        for (int j = 0; j < 16; j++) w[j] = up_w[j * DH + c];
        float bb = up_b[c];
        for (int r = 0; r < 128; r++) {
            float acc = bb;
            const float* xr = xs + r * 16;
#pragma unroll
            for (int j = 0; j < 16; j++) acc += xr[j] * w[j];
            size_t o = ((size_t)bidx * T_LEN + t0 + r) * DH + c;
            g_h[o] = acc;
            __nv_bfloat16 hi = __float2bfloat16(acc);
            g_hhi[o] = hi;
            g_hlo[o] = __float2bfloat16(acc - __bfloat162float(hi));
        }
        __syncthreads();
        if (tid == 0) red_rel_add(&g_udone[bidx * 8 + ttile]);
        return;
    }

    // ===== GEMM section: layer-major =====
    int rem = id - FRONT;
    int layer = 0;
    while (layer < NL - 1 && rem >= c_convn[layer] + c_skipn[layer]) {
        rem -= c_convn[layer] + c_skipn[layer];
        layer++;
    }
    const int tstart = c_ts[layer];
    const int nt = 8 - tstart;
    const bool isconv = rem < c_convn[layer];

    const int wid = tid >> 5, lid = tid & 31;
    const int wm = wid & 3, wn = wid >> 2;          // warp tile 32x32
    const uint32_t smb = cvta_s(sm);
    const int lrow = lid & 15, khalf = lid >> 4;
    const int lc = tid & 3, lislo = (tid >> 2) & 1, lrr = tid >> 3;
    const int chunk = lislo * 4 + lc;

    float acc[2][4][4];
#pragma unroll
    for (int a = 0; a < 2; a++)
#pragma unroll
        for (int b = 0; b < 4; b++)
#pragma unroll
            for (int d = 0; d < 4; d++) acc[a][b][d] = 0.0f;

    if (isconv) {
        const int nx = rem & 7;
        const int y = rem >> 3;
        const int bidx = y / nt;
        const int ttile = tstart + y % nt;
        const int n0 = nx * 64;
        const int m0 = bidx * T_LEN + ttile * 128;
        const int t0 = ttile * 128;
        const int dil = 1 << layer;

        if (tid == 0) {
            spin_ge(&g_wc[layer], 192);
            if (layer == 0) {
                spin_ge(&g_udone[bidx * 8 + ttile], 1);
                spin_ge(&g_udone[bidx * 8 + ttile - 1], 1);
            } else {
                int lo = ttile - 2, tsp = c_ts[layer - 1];
                if (lo < tsp) lo = tsp;
                for (int tp = lo; tp <= ttile; tp++) {
                    int tgt = (tp == 7) ? 8 : 4;
                    spin_ge(&g_sdone[((layer - 1) * B_SZ + bidx) * 8 + tp], tgt);
                }
            }
        }
        __syncthreads();

        auto issue = [&](int it, uint32_t stgoff) {
            int tap = it >> 3, kc = it & 7;
            int kk = kc * 32;
            int off = (2 - tap) * dil;
            const __nv_bfloat16* Asrc = (lislo ? g_hlo : g_hhi)
                                      + ((long)(m0 - off) * DH + kk) + lc * 8;
            const __nv_bfloat16* Bsrc = (lislo ? g_Wc_lo : g_Wc_hi)
                                      + ((size_t)(layer * 3 + tap) * 512 + n0) * DH + kk + lc * 8;
            uint32_t sb = smb + stgoff;
#pragma unroll
            for (int q = 0; q < 4; q++) {
                int r = q * 32 + lrr;
                cp16(sb + SWA(r, chunk), Asrc + (size_t)r * DH, (t0 + r) >= off);
            }
#pragma unroll
            for (int q = 0; q < 2; q++) {
                int r = q * 32 + lrr;
                cp16(sb + SP_B + SWA(r, chunk), Bsrc + (size_t)r * DH, true);
            }
            CP_COMMIT();
        };
        auto compute = [&](uint32_t s0) {
#pragma unroll
            for (int ks = 0; ks < 2; ks++) {
                int ch = 2 * ks + khalf;
                uint32_t a[2][4], bH[2][4], bL[2][4];
#pragma unroll
                for (int q = 0; q < 2; q++) {
                    int rB = wn * 32 + q * 16 + lrow;
                    ldsm4(bH[q], s0 + SP_B + SWA(rB, ch));
                    ldsm4(bL[q], s0 + SP_B + SWA(rB, ch + 4));
                }
#pragma unroll
                for (int mt = 0; mt < 2; mt++)
                    ldsm4(a[mt], s0 + SWA(wm * 32 + mt * 16 + lrow, ch));
#pragma unroll
                for (int mt = 0; mt < 2; mt++)
#pragma unroll
                    for (int nn = 0; nn < 4; nn++) {
                        int q = nn >> 1, h = nn & 1;
                        mma16816(acc[mt][nn], a[mt], bH[q][h], bH[q][h + 2]);
                        mma16816(acc[mt][nn], a[mt], bL[q][h], bL[q][h + 2]);
                    }
#pragma unroll
                for (int mt = 0; mt < 2; mt++)
                    ldsm4(a[mt], s0 + SWA(wm * 32 + mt * 16 + lrow, ch + 4));
#pragma unroll
                for (int mt = 0; mt < 2; mt++)
#pragma unroll
                    for (int nn = 0; nn < 4; nn++) {
                        int q = nn >> 1, h = nn & 1;
                        mma16816(acc[mt][nn], a[mt], bH[q][h], bH[q][h + 2]);
                    }
            }
        };

        issue(0, 0);
        issue(1, STG_SZ);
        for (int mj = 0; mj < 7; mj++) {
            CP_WAIT1(); __syncthreads(); issue(mj * 3 + 2, 2 * STG_SZ); compute(smb);
            CP_WAIT1(); __syncthreads(); issue(mj * 3 + 3, 0);          compute(smb + STG_SZ);
            CP_WAIT1(); __syncthreads(); issue(mj * 3 + 4, STG_SZ);     compute(smb + 2 * STG_SZ);
        }
        CP_WAIT1(); __syncthreads(); issue(23, 2 * STG_SZ); compute(smb);
        CP_WAIT1(); __syncthreads();                         compute(smb + STG_SZ);
        CP_WAIT0(); __syncthreads();                         compute(smb + 2 * STG_SZ);

        const float* cbf = conv_b + layer * 512;
        const int lm = lid >> 2, ln = lid & 3;
#pragma unroll
        for (int mt = 0; mt < 2; mt++) {
            int row0 = m0 + wm * 32 + mt * 16 + lm;
#pragma unroll
            for (int nn = 0; nn < 4; nn++) {
                int ch = ((n0 + wn * 32 + nn * 8) >> 1) + ln;
                float fb = __ldg(cbf + ch), gb = __ldg(cbf + 256 + ch);
#pragma unroll
                for (int u = 0; u < 2; u++) {
                    int row = row0 + u * 8;
                    float f = acc[mt][nn][2 * u] + fb;
                    float g = acc[mt][nn][2 * u + 1] + gb;
                    float e2f = __expf(2.0f * f);
                    float th = (e2f - 1.0f) / (e2f + 1.0f);
                    float val = th / (1.0f + __expf(-g));
                    __nv_bfloat16 hi = __float2bfloat16(val);
                    g_ghi[(size_t)row * DH + ch] = hi;
                    g_glo[(size_t)row * DH + ch] = __float2bfloat16(val - __bfloat162float(hi));
                }
            }
        }
        __syncthreads();
        if (tid == 0) red_rel_add(&g_cdone[(layer * B_SZ + bidx) * 8 + ttile]);
    } else {
        int s = rem - c_convn[layer];
        const int x = s & 3;
        int jj, bb;
        if (layer == NL - 1) { bb = s >> 2; jj = nt; }          // L7: skip-half only
        else { bb = (s >> 2) / (nt + 1); jj = (s >> 2) % (nt + 1); }
        const int ttile = (jj < nt) ? (tstart + jj) : 7;
        const int n0 = ((jj < nt) ? 0 : 256) + x * 64;
        const int m0 = bb * T_LEN + ttile * 128;

        if (tid == 0) {
            spin_ge(&g_ws[layer], 64);
            int hi_t = ttile + 2;
            if (hi_t > 7) hi_t = 7;
            for (int tp = ttile; tp <= hi_t; tp++)
                spin_ge(&g_cdone[(layer * B_SZ + bb) * 8 + tp], 8);
        }
        __syncthreads();

        const __nv_bfloat16* Asrc = (lislo ? g_glo : g_ghi) + (size_t)m0 * DH + lc * 8;
        const __nv_bfloat16* Bsrc = (lislo ? g_Ws_lo : g_Ws_hi)
                                  + ((size_t)layer * 512 + n0) * DH + lc * 8;

        auto issue = [&](int it, uint32_t stgoff) {
            int kk = it * 32;
            uint32_t sb = smb + stgoff;
#pragma unroll
            for (int q = 0; q < 4; q++) {
                int r = q * 32 + lrr;
                cp16(sb + SWA(r, chunk), Asrc + (size_t)r * DH + kk, true);
            }
#pragma unroll
            for (int q = 0; q < 2; q++) {
                int r = q * 32 + lrr;
                cp16(sb + SP_B + SWA(r, chunk), Bsrc + (size_t)r * DH + kk, true);
            }
            CP_COMMIT();
        };
        auto compute = [&](uint32_t s0) {
#pragma unroll
            for (int ks = 0; ks < 2; ks++) {
                int ch = 2 * ks + khalf;
                uint32_t a[2][4], bH[2][4], bL[2][4];
#pragma unroll
                for (int q = 0; q < 2; q++) {
                    int rB = wn * 32 + q * 16 + lrow;
                    ldsm4(bH[q], s0 + SP_B + SWA(rB, ch));
                    ldsm4(bL[q], s0 + SP_B + SWA(rB, ch + 4));
                }
#pragma unroll
                for (int mt = 0; mt < 2; mt++)
                    ldsm4(a[mt], s0 + SWA(wm * 32 + mt * 16 + lrow, ch));
#pragma unroll
                for (int mt = 0; mt < 2; mt++)
#pragma unroll
                    for (int nn = 0; nn < 4; nn++) {
                        int q = nn >> 1, h = nn & 1;
                        mma16816(acc[mt][nn], a[mt], bH[q][h], bH[q][h + 2]);
                        mma16816(acc[mt][nn], a[mt], bL[q][h], bL[q][h + 2]);
                    }
#pragma unroll
                for (int mt = 0; mt < 2; mt++)
                    ldsm4(a[mt], s0 + SWA(wm * 32 + mt * 16 + lrow, ch + 4));
#pragma unroll
                for (int mt = 0; mt < 2; mt++)
#pragma unroll
                    for (int nn = 0; nn < 4; nn++) {
                        int q = nn >> 1, h = nn & 1;
                        mma16816(acc[mt][nn], a[mt], bH[q][h], bH[q][h + 2]);
                    }
            }
        };

        issue(0, 0);
        issue(1, STG_SZ);
        CP_WAIT1(); __syncthreads(); issue(2, 2 * STG_SZ); compute(smb);
        CP_WAIT1(); __syncthreads(); issue(3, 0);          compute(smb + STG_SZ);
        CP_WAIT1(); __syncthreads(); issue(4, STG_SZ);     compute(smb + 2 * STG_SZ);
        CP_WAIT1(); __syncthreads(); issue(5, 2 * STG_SZ); compute(smb);
        CP_WAIT1(); __syncthreads(); issue(6, 0);          compute(smb + STG_SZ);
        CP_WAIT1(); __syncthreads(); issue(7, STG_SZ);     compute(smb + 2 * STG_SZ);
        CP_WAIT1(); __syncthreads();                       compute(smb);
        CP_WAIT0(); __syncthreads();                       compute(smb + STG_SZ);

        const float* sb_ = skip_b + layer * 512;
        const int lm = lid >> 2, ln = lid & 3;
        const bool is_h = (n0 < 256);
#pragma unroll
        for (int mt = 0; mt < 2; mt++) {
            int row0 = m0 + wm * 32 + mt * 16 + lm;
#pragma unroll
            for (int nn = 0; nn < 4; nn++) {
                int oc = n0 + wn * 32 + nn * 8 + 2 * ln;
                float b0 = __ldg(sb_ + oc), b1 = __ldg(sb_ + oc + 1);
#pragma unroll
                for (int u = 0; u < 2; u++) {
                    int row = row0 + u * 8;
                    float v0 = acc[mt][nn][2 * u] + b0;
                    float v1 = acc[mt][nn][2 * u + 1] + b1;
                    if (is_h) {
                        float2* hp = (float2*)(g_h + (size_t)row * DH + oc);
                        float2 cur = *hp;
                        float nh0 = cur.x + v0, nh1 = cur.y + v1;
                        *hp = make_float2(nh0, nh1);
                        __nv_bfloat16 a0 = __float2bfloat16(nh0);
                        __nv_bfloat16 a1 = __float2bfloat16(nh1);
                        *(__nv_bfloat162*)(g_hhi + (size_t)row * DH + oc) = __nv_bfloat162(a0, a1);
                        *(__nv_bfloat162*)(g_hlo + (size_t)row * DH + oc) = __nv_bfloat162(
                            __float2bfloat16(nh0 - __bfloat162float(a0)),
                            __float2bfloat16(nh1 - __bfloat162float(a1)));
                    } else {
                        float2* sp = (float2*)(g_skip + (size_t)row * DH + (oc - 256));
                        float2 prev = (layer == 0) ? make_float2(0.f, 0.f) : *sp;
                        *sp = make_float2(prev.x + v0, prev.y + v1);
                    }
                }
            }
        }
        __syncthreads();
        if (tid == 0) red_rel_add(&g_sdone[(layer * B_SZ + bb) * 8 + ttile]);
    }
}

// ---------------- FC head + Gaussian NLL ------------------------------------
__global__ __launch_bounds__(256) void final_k(
    const float* __restrict__ y,
    const float* __restrict__ fc_w, const float* __restrict__ fc_b,
    const float* __restrict__ loc_w, const float* __restrict__ loc_b,
    const float* __restrict__ scale_w, const float* __restrict__ scale_b,
    float* __restrict__ out) {
    int row = blockIdx.x;
    int tt = row >> 6;
    int b = row & 63;
    int t = T_LEN - OUTL + tt;
    size_t r = (size_t)b * T_LEN + t;
    __shared__ float srow[DH];
    __shared__ float red[256];
    int c = threadIdx.x;
    srow[c] = g_skip[r * DH + c];
    __syncthreads();
    float acc = fc_b[c];
#pragma unroll 8
    for (int k = 0; k < DH; k++) acc += srow[k] * fc_w[k * DH + c];
    float ff = fmaxf(acc, 0.0f);

    red[c] = ff * loc_w[c];
    __syncthreads();
    for (int s = 128; s > 0; s >>= 1) {
        if (c < s) red[c] += red[c + s];
        __syncthreads();
    }
    float loc = red[0] + loc_b[0];
    __syncthreads();

    red[c] = ff * scale_w[c];
    __syncthreads();
    for (int s = 128; s > 0; s >>= 1) {
        if (c < s) red[c] += red[c + s];
        __syncthreads();
    }
    if (c == 0) {
        float sraw = red[0] + scale_b[0];
        float sp = (sraw > 20.0f) ? sraw : log1pf(expf(sraw));
        float scale = sp + 1e-6f;
        float yt = y[(size_t)t * B_SZ + b];
        float z = (yt - loc) / scale;
        float lp = -0.5f * z * z - logf(scale) - 0.91893853320467274f;
        out[2 + row] = loc;
        out[2 + OUTL * B_SZ + row] = scale;
        atomicAdd(&g_loss, lp);
    }
}

__global__ void finish_k(float* __restrict__ out) {
    float L = -g_loss / (float)(OUTL * B_SZ);
    out[0] = L;
    out[1] = L;
}

// ---------------- launch -----------------------------------------------------
extern "C" void kernel_launch(void* const* d_in, const int* in_sizes, int n_in,
                              void* d_out, int out_size) {
    const float* X_cov   = (const float*)d_in[1];
    const float* X_lag   = (const float*)d_in[2];
    const float* y       = (const float*)d_in[3];
    const float* up_w    = (const float*)d_in[5];
    const float* up_b    = (const float*)d_in[6];
    const float* conv_w  = (const float*)d_in[7];
    const float* conv_b  = (const float*)d_in[8];
    const float* skip_w  = (const float*)d_in[9];
    const float* skip_b  = (const float*)d_in[10];
    const float* fc_w    = (const float*)d_in[11];
    const float* fc_b    = (const float*)d_in[12];
    const float* loc_w   = (const float*)d_in[13];
    const float* loc_b   = (const float*)d_in[14];
    const float* scale_w = (const float*)d_in[15];
    const float* scale_b = (const float*)d_in[16];
    float* out = (float*)d_out;

    cudaFuncSetAttribute(mega, cudaFuncAttributeMaxDynamicSharedMemorySize, SMEM_DYN);

    init_k<<<(NL * B_SZ * 8 + 255) / 256, 256>>>();
    mega<<<MEGA_BLOCKS, 256, SMEM_DYN>>>(conv_w, skip_w, X_lag, X_cov,
                                         up_w, up_b, conv_b, skip_b);
    final_k<<<OUTL * B_SZ, 256>>>(y, fc_w, fc_b, loc_w, loc_b, scale_w, scale_b, out);
    finish_k<<<1, 1>>>(out);
}

// round 16
// speedup vs baseline: 1.7010x; 1.0036x over previous
#include <cuda_runtime.h>
#include <cuda_bf16.h>
#include <cstdint>
#include <math.h>

#define T_LEN 1024
#define B_SZ  64
#define DH    256
#define NL    8
#define OUTL  24
#define M_TOT (B_SZ * T_LEN)
#define UP_T0_TILE 2              // up computed for t-tiles 2..7

// ---------------- device scratch -------------------------------------------
__device__ __align__(128) float          g_h   [M_TOT * DH];
__device__ __align__(128) float          g_skip[M_TOT * DH];
__device__ __align__(128) __nv_bfloat16  g_hhi [M_TOT * DH];
__device__ __align__(128) __nv_bfloat16  g_hlo [M_TOT * DH];
__device__ __align__(128) __nv_bfloat16  g_ghi [M_TOT * DH];
__device__ __align__(128) __nv_bfloat16  g_glo [M_TOT * DH];
__device__ __align__(128) __nv_bfloat16  g_Wc_hi[NL * 3 * 512 * DH];
__device__ __align__(128) __nv_bfloat16  g_Wc_lo[NL * 3 * 512 * DH];
__device__ __align__(128) __nv_bfloat16  g_Ws_hi[NL * 512 * DH];
__device__ __align__(128) __nv_bfloat16  g_Ws_lo[NL * 512 * DH];
__device__ float g_loss;
// dependency flags
__device__ int g_cdone[NL * B_SZ * 8];
__device__ int g_sdone[NL * B_SZ * 8];
__device__ int g_udone[B_SZ * 8];
__device__ int g_wc[NL];
__device__ int g_ws[NL];
__device__ int g_fdone;

// layer-major schedule, L7 skip h-half dropped
__constant__ int c_ts[NL]    = {3, 3, 3, 4, 4, 4, 5, 7};
__constant__ int c_convn[NL] = {2560, 2560, 2560, 2048, 2048, 2048, 1536, 512};
__constant__ int c_skipn[NL] = {1536, 1536, 1536, 1280, 1280, 1280, 1024, 256};
// front: conv-w prep 8*192, skip-w prep 8*64, up 64*6
#define N_PREP_C 1536
#define N_PREP_S 512
#define N_UP     384
#define FRONT    (N_PREP_C + N_PREP_S + N_UP)   // 2432
#define N_GEMM_CONV 15872
#define N_GEMM_SKIP 9728
#define N_GEMM   (N_GEMM_CONV + N_GEMM_SKIP)     // 25600
#define N_FINAL  (OUTL * B_SZ)                   // 1536
#define MEGA_BLOCKS (FRONT + N_GEMM + N_FINAL + 1)  // 29569

// ---------------- PTX helpers ------------------------------------------------
__device__ __forceinline__ uint32_t cvta_s(const void* p) {
    uint32_t a;
    asm("{ .reg .u64 t; cvta.to.shared.u64 t, %1; cvt.u32.u64 %0, t; }" : "=r"(a) : "l"(p));
    return a;
}
__device__ __forceinline__ void ldsm4(uint32_t (&r)[4], uint32_t addr) {
    asm volatile("ldmatrix.sync.aligned.m8n8.x4.shared.b16 {%0,%1,%2,%3}, [%4];"
                 : "=r"(r[0]), "=r"(r[1]), "=r"(r[2]), "=r"(r[3]) : "r"(addr));
}
__device__ __forceinline__ void mma16816(float (&c)[4], const uint32_t (&a)[4],
                                         uint32_t b0, uint32_t b1) {
    asm volatile(
        "mma.sync.aligned.m16n8k16.row.col.f32.bf16.bf16.f32 "
        "{%0,%1,%2,%3}, {%4,%5,%6,%7}, {%8,%9}, {%0,%1,%2,%3};"
        : "+f"(c[0]), "+f"(c[1]), "+f"(c[2]), "+f"(c[3])
        : "r"(a[0]), "r"(a[1]), "r"(a[2]), "r"(a[3]), "r"(b0), "r"(b1));
}
__device__ __forceinline__ void cp16(uint32_t saddr, const void* g, bool pred) {
    int sz = pred ? 16 : 0;
    asm volatile("cp.async.cg.shared.global [%0], [%1], 16, %2;"
                 :: "r"(saddr), "l"(g), "r"(sz) : "memory");
}
#define CP_COMMIT() asm volatile("cp.async.commit_group;" ::: "memory")
#define CP_WAIT1()  asm volatile("cp.async.wait_group 1;" ::: "memory")
#define CP_WAIT0()  asm volatile("cp.async.wait_group 0;" ::: "memory")

__device__ __forceinline__ int ld_acq(const int* p) {
    int v;
    asm volatile("ld.acquire.gpu.global.b32 %0, [%1];" : "=r"(v) : "l"(p) : "memory");
    return v;
}
__device__ __forceinline__ void red_rel_add(int* p) {
    asm volatile("red.release.gpu.global.add.s32 [%0], 1;" :: "l"(p) : "memory");
}
__device__ __forceinline__ void spin_ge(const int* p, int tgt) {
    while (ld_acq(p) < tgt) __nanosleep(64);
}

// Stage: superplane A @0 (128 rows x 128B = [hi|lo]), B @16KB (64 rows x 128B).
#define SP_B  16384
#define STG_SZ 24576
#define SMEM_DYN (3 * STG_SZ)
#define SWA(r, c) ((uint32_t)((r) * 128 + (((c) ^ ((r) & 7)) << 4)))

// ---------------- init: zero flags ------------------------------------------
__global__ void init_k() {
    int idx = blockIdx.x * blockDim.x + threadIdx.x;
    if (idx == 0) { g_loss = 0.0f; g_fdone = 0; }
    if (idx < NL * B_SZ * 8) { g_cdone[idx] = 0; g_sdone[idx] = 0; }
    if (idx < B_SZ * 8) g_udone[idx] = 0;
    if (idx < NL) { g_wc[idx] = 0; g_ws[idx] = 0; }
}

// ---------------- mega kernel ------------------------------------------------
__global__ __launch_bounds__(256, 3) void mega(
    const float* __restrict__ conv_w, const float* __restrict__ skip_w,
    const float* __restrict__ X_lag,  const float* __restrict__ X_cov,
    const float* __restrict__ up_w,   const float* __restrict__ up_b,
    const float* __restrict__ conv_b, const float* __restrict__ skip_b,
    const float* __restrict__ y,
    const float* __restrict__ fc_w,   const float* __restrict__ fc_b,
    const float* __restrict__ loc_w,  const float* __restrict__ loc_b,
    const float* __restrict__ scale_w, const float* __restrict__ scale_b,
    float* __restrict__ out) {
    extern __shared__ __align__(16) unsigned char sm[];
    const int tid = threadIdx.x;
    int id = blockIdx.x;

    // ===== front section: weight prep + up projection =====
    if (id < N_PREP_C) {
        int layer = id / 192;
        int base = (id % 192) * 2048;
#pragma unroll
        for (int e = 0; e < 8; e++) {
            int loc = base + tid * 8 + e;
            int ic = loc & 255;
            int np = (loc >> 8) & 511;
            int tap = loc >> 17;
            int c = np >> 1, s = np & 1;
            int oc = c + s * 256;
            size_t gidx = (size_t)layer * (3 * 512 * 256) + loc;
            float v = conv_w[((size_t)(layer * 512 + oc) * DH + ic) * 3 + tap];
            __nv_bfloat16 hi = __float2bfloat16(v);
            g_Wc_hi[gidx] = hi;
            g_Wc_lo[gidx] = __float2bfloat16(v - __bfloat162float(hi));
        }
        __syncthreads();
        if (tid == 0) red_rel_add(&g_wc[layer]);
        return;
    }
    if (id < N_PREP_C + N_PREP_S) {
        id -= N_PREP_C;
        int layer = id / 64;
        int base = (id % 64) * 2048;
#pragma unroll
        for (int e = 0; e < 8; e++) {
            int loc = base + tid * 8 + e;
            size_t gidx = (size_t)layer * (512 * 256) + loc;
            float v = skip_w[gidx];
            __nv_bfloat16 hi = __float2bfloat16(v);
            g_Ws_hi[gidx] = hi;
            g_Ws_lo[gidx] = __float2bfloat16(v - __bfloat162float(hi));
        }
        __syncthreads();
        if (tid == 0) red_rel_add(&g_ws[layer]);
        return;
    }
    if (id < FRONT) {
        id -= N_PREP_C + N_PREP_S;
        int bidx = id / 6;
        int ttile = UP_T0_TILE + id % 6;
        int t0 = ttile * 128;
        float* xs = (float*)sm;   // [128][16]
#pragma unroll
        for (int i = 0; i < 8; i++) {
            int e = tid + i * 256;
            int r = e >> 4, j = e & 15;
            int t = t0 + r;
            xs[e] = (j < 8) ? X_lag[((size_t)t * B_SZ + bidx) * 8 + j]
                            : X_cov[((size_t)t * B_SZ + bidx) * 8 + (j - 8)];
        }
        __syncthreads();
        int c = tid;
        float w[16];
#pragma unroll
        for (int j = 0; j < 16; j++) w[j] = up_w[j * DH + c];
        float bb = up_b[c];
        for (int r = 0; r < 128; r++) {
            float acc = bb;
            const float* xr = xs + r * 16;
#pragma unroll
            for (int j = 0; j < 16; j++) acc += xr[j] * w[j];
            size_t o = ((size_t)bidx * T_LEN + t0 + r) * DH + c;
            g_h[o] = acc;
            __nv_bfloat16 hi = __float2bfloat16(acc);
            g_hhi[o] = hi;
            g_hlo[o] = __float2bfloat16(acc - __bfloat162float(hi));
        }
        __syncthreads();
        if (tid == 0) red_rel_add(&g_udone[bidx * 8 + ttile]);
        return;
    }

    // ===== tail section: FC head + Gaussian NLL + finish =====
    if (id >= FRONT + N_GEMM) {
        int row = id - (FRONT + N_GEMM);
        if (row == N_FINAL) {
            // finish block
            if (tid == 0) {
                spin_ge(&g_fdone, N_FINAL);
                float L = -g_loss / (float)(OUTL * B_SZ);
                out[0] = L;
                out[1] = L;
            }
            return;
        }
        int tt = row >> 6;
        int b = row & 63;
        int t = T_LEN - OUTL + tt;
        size_t r = (size_t)b * T_LEN + t;
        if (tid == 0) spin_ge(&g_sdone[(7 * B_SZ + b) * 8 + 7], 4);
        __syncthreads();
        float* srow = (float*)sm;           // [256]
        float* red  = (float*)sm + 256;     // [256]
        int c = tid;
        srow[c] = g_skip[r * DH + c];
        __syncthreads();
        float acc = fc_b[c];
#pragma unroll 8
        for (int k = 0; k < DH; k++) acc += srow[k] * fc_w[k * DH + c];
        float ff = fmaxf(acc, 0.0f);

        red[c] = ff * loc_w[c];
        __syncthreads();
        for (int s = 128; s > 0; s >>= 1) {
            if (c < s) red[c] += red[c + s];
            __syncthreads();
        }
        float loc = red[0] + loc_b[0];
        __syncthreads();

        red[c] = ff * scale_w[c];
        __syncthreads();
        for (int s = 128; s > 0; s >>= 1) {
            if (c < s) red[c] += red[c + s];
            __syncthreads();
        }
        if (c == 0) {
            float sraw = red[0] + scale_b[0];
            float sp = (sraw > 20.0f) ? sraw : log1pf(expf(sraw));
            float scale = sp + 1e-6f;
            float yt = y[(size_t)t * B_SZ + b];
            float z = (yt - loc) / scale;
            float lp = -0.5f * z * z - logf(scale) - 0.91893853320467274f;
            out[2 + row] = loc;
            out[2 + OUTL * B_SZ + row] = scale;
            atomicAdd(&g_loss, lp);
            red_rel_add(&g_fdone);
        }
        return;
    }

    // ===== GEMM section: layer-major =====
    int rem = id - FRONT;
    int layer = 0;
    while (layer < NL - 1 && rem >= c_convn[layer] + c_skipn[layer]) {
        rem -= c_convn[layer] + c_skipn[layer];
        layer++;
    }
    const int tstart = c_ts[layer];
    const int nt = 8 - tstart;
    const bool isconv = rem < c_convn[layer];

    const int wid = tid >> 5, lid = tid & 31;
    const int wm = wid & 3, wn = wid >> 2;          // warp tile 32x32
    const uint32_t smb = cvta_s(sm);
    const int lrow = lid & 15, khalf = lid >> 4;
    const int lc = tid & 3, lislo = (tid >> 2) & 1, lrr = tid >> 3;
    const int chunk = lislo * 4 + lc;

    float acc[2][4][4];
#pragma unroll
    for (int a = 0; a < 2; a++)
#pragma unroll
        for (int b = 0; b < 4; b++)
#pragma unroll
            for (int d = 0; d < 4; d++) acc[a][b][d] = 0.0f;

    if (isconv) {
        const int nx = rem & 7;
        const int y2 = rem >> 3;
        const int bidx = y2 / nt;
        const int ttile = tstart + y2 % nt;
        const int n0 = nx * 64;
        const int m0 = bidx * T_LEN + ttile * 128;
        const int t0 = ttile * 128;
        const int dil = 1 << layer;

        if (tid == 0) {
            spin_ge(&g_wc[layer], 192);
            if (layer == 0) {
                spin_ge(&g_udone[bidx * 8 + ttile], 1);
                spin_ge(&g_udone[bidx * 8 + ttile - 1], 1);
            } else {
                int lo = ttile - 2, tsp = c_ts[layer - 1];
                if (lo < tsp) lo = tsp;
                for (int tp = lo; tp <= ttile; tp++) {
                    int tgt = (tp == 7) ? 8 : 4;
                    spin_ge(&g_sdone[((layer - 1) * B_SZ + bidx) * 8 + tp], tgt);
                }
            }
        }
        __syncthreads();

        auto issue = [&](int it, uint32_t stgoff) {
            int tap = it >> 3, kc = it & 7;
            int kk = kc * 32;
            int off = (2 - tap) * dil;
            const __nv_bfloat16* Asrc = (lislo ? g_hlo : g_hhi)
                                      + ((long)(m0 - off) * DH + kk) + lc * 8;
            const __nv_bfloat16* Bsrc = (lislo ? g_Wc_lo : g_Wc_hi)
                                      + ((size_t)(layer * 3 + tap) * 512 + n0) * DH + kk + lc * 8;
            uint32_t sb = smb + stgoff;
#pragma unroll
            for (int q = 0; q < 4; q++) {
                int r = q * 32 + lrr;
                cp16(sb + SWA(r, chunk), Asrc + (size_t)r * DH, (t0 + r) >= off);
            }
#pragma unroll
            for (int q = 0; q < 2; q++) {
                int r = q * 32 + lrr;
                cp16(sb + SP_B + SWA(r, chunk), Bsrc + (size_t)r * DH, true);
            }
            CP_COMMIT();
        };
        auto compute = [&](uint32_t s0) {
#pragma unroll
            for (int ks = 0; ks < 2; ks++) {
                int ch = 2 * ks + khalf;
                uint32_t a[2][4], bH[2][4], bL[2][4];
#pragma unroll
                for (int q = 0; q < 2; q++) {
                    int rB = wn * 32 + q * 16 + lrow;
                    ldsm4(bH[q], s0 + SP_B + SWA(rB, ch));
                    ldsm4(bL[q], s0 + SP_B + SWA(rB, ch + 4));
                }
#pragma unroll
                for (int mt = 0; mt < 2; mt++)
                    ldsm4(a[mt], s0 + SWA(wm * 32 + mt * 16 + lrow, ch));
#pragma unroll
                for (int mt = 0; mt < 2; mt++)
#pragma unroll
                    for (int nn = 0; nn < 4; nn++) {
                        int q = nn >> 1, h = nn & 1;
                        mma16816(acc[mt][nn], a[mt], bH[q][h], bH[q][h + 2]);
                        mma16816(acc[mt][nn], a[mt], bL[q][h], bL[q][h + 2]);
                    }
#pragma unroll
                for (int mt = 0; mt < 2; mt++)
                    ldsm4(a[mt], s0 + SWA(wm * 32 + mt * 16 + lrow, ch + 4));
#pragma unroll
                for (int mt = 0; mt < 2; mt++)
#pragma unroll
                    for (int nn = 0; nn < 4; nn++) {
                        int q = nn >> 1, h = nn & 1;
                        mma16816(acc[mt][nn], a[mt], bH[q][h], bH[q][h + 2]);
                    }
            }
        };

        issue(0, 0);
        issue(1, STG_SZ);
        for (int mj = 0; mj < 7; mj++) {
            CP_WAIT1(); __syncthreads(); issue(mj * 3 + 2, 2 * STG_SZ); compute(smb);
            CP_WAIT1(); __syncthreads(); issue(mj * 3 + 3, 0);          compute(smb + STG_SZ);
            CP_WAIT1(); __syncthreads(); issue(mj * 3 + 4, STG_SZ);     compute(smb + 2 * STG_SZ);
        }
        CP_WAIT1(); __syncthreads(); issue(23, 2 * STG_SZ); compute(smb);
        CP_WAIT1(); __syncthreads();                         compute(smb + STG_SZ);
        CP_WAIT0(); __syncthreads();                         compute(smb + 2 * STG_SZ);

        const float* cbf = conv_b + layer * 512;
        const int lm = lid >> 2, ln = lid & 3;
#pragma unroll
        for (int mt = 0; mt < 2; mt++) {
            int row0 = m0 + wm * 32 + mt * 16 + lm;
#pragma unroll
            for (int nn = 0; nn < 4; nn++) {
                int ch = ((n0 + wn * 32 + nn * 8) >> 1) + ln;
                float fb = __ldg(cbf + ch), gb = __ldg(cbf + 256 + ch);
#pragma unroll
                for (int u = 0; u < 2; u++) {
                    int row = row0 + u * 8;
                    float f = acc[mt][nn][2 * u] + fb;
                    float g = acc[mt][nn][2 * u + 1] + gb;
                    float e2f = __expf(2.0f * f);
                    float th = (e2f - 1.0f) / (e2f + 1.0f);
                    float val = th / (1.0f + __expf(-g));
                    __nv_bfloat16 hi = __float2bfloat16(val);
                    g_ghi[(size_t)row * DH + ch] = hi;
                    g_glo[(size_t)row * DH + ch] = __float2bfloat16(val - __bfloat162float(hi));
                }
            }
        }
        __syncthreads();
        if (tid == 0) red_rel_add(&g_cdone[(layer * B_SZ + bidx) * 8 + ttile]);
    } else {
        int s = rem - c_convn[layer];
        const int x = s & 3;
        int jj, bb;
        if (layer == NL - 1) { bb = s >> 2; jj = nt; }          // L7: skip-half only
        else { bb = (s >> 2) / (nt + 1); jj = (s >> 2) % (nt + 1); }
        const int ttile = (jj < nt) ? (tstart + jj) : 7;
        const int n0 = ((jj < nt) ? 0 : 256) + x * 64;
        const int m0 = bb * T_LEN + ttile * 128;

        if (tid == 0) {
            spin_ge(&g_ws[layer], 64);
            int hi_t = ttile + 2;
            if (hi_t > 7) hi_t = 7;
            for (int tp = ttile; tp <= hi_t; tp++)
                spin_ge(&g_cdone[(layer * B_SZ + bb) * 8 + tp], 8);
        }
        __syncthreads();

        const __nv_bfloat16* Asrc = (lislo ? g_glo : g_ghi) + (size_t)m0 * DH + lc * 8;
        const __nv_bfloat16* Bsrc = (lislo ? g_Ws_lo : g_Ws_hi)
                                  + ((size_t)layer * 512 + n0) * DH + lc * 8;

        auto issue = [&](int it, uint32_t stgoff) {
            int kk = it * 32;
            uint32_t sb = smb + stgoff;
#pragma unroll
            for (int q = 0; q < 4; q++) {
                int r = q * 32 + lrr;
                cp16(sb + SWA(r, chunk), Asrc + (size_t)r * DH + kk, true);
            }
#pragma unroll
            for (int q = 0; q < 2; q++) {
                int r = q * 32 + lrr;
                cp16(sb + SP_B + SWA(r, chunk), Bsrc + (size_t)r * DH + kk, true);
            }
            CP_COMMIT();
        };
        auto compute = [&](uint32_t s0) {
#pragma unroll
            for (int ks = 0; ks < 2; ks++) {
                int ch = 2 * ks + khalf;
                uint32_t a[2][4], bH[2][4], bL[2][4];
#pragma unroll
                for (int q = 0; q < 2; q++) {
                    int rB = wn * 32 + q * 16 + lrow;
                    ldsm4(bH[q], s0 + SP_B + SWA(rB, ch));
                    ldsm4(bL[q], s0 + SP_B + SWA(rB, ch + 4));
                }
#pragma unroll
                for (int mt = 0; mt < 2; mt++)
                    ldsm4(a[mt], s0 + SWA(wm * 32 + mt * 16 + lrow, ch));
#pragma unroll
                for (int mt = 0; mt < 2; mt++)
#pragma unroll
                    for (int nn = 0; nn < 4; nn++) {
                        int q = nn >> 1, h = nn & 1;
                        mma16816(acc[mt][nn], a[mt], bH[q][h], bH[q][h + 2]);
                        mma16816(acc[mt][nn], a[mt], bL[q][h], bL[q][h + 2]);
                    }
#pragma unroll
                for (int mt = 0; mt < 2; mt++)
                    ldsm4(a[mt], s0 + SWA(wm * 32 + mt * 16 + lrow, ch + 4));
#pragma unroll
                for (int mt = 0; mt < 2; mt++)
#pragma unroll
                    for (int nn = 0; nn < 4; nn++) {
                        int q = nn >> 1, h = nn & 1;
                        mma16816(acc[mt][nn], a[mt], bH[q][h], bH[q][h + 2]);
                    }
            }
        };

        issue(0, 0);
        issue(1, STG_SZ);
        CP_WAIT1(); __syncthreads(); issue(2, 2 * STG_SZ); compute(smb);
        CP_WAIT1(); __syncthreads(); issue(3, 0);          compute(smb + STG_SZ);
        CP_WAIT1(); __syncthreads(); issue(4, STG_SZ);     compute(smb + 2 * STG_SZ);
        CP_WAIT1(); __syncthreads(); issue(5, 2 * STG_SZ); compute(smb);
        CP_WAIT1(); __syncthreads(); issue(6, 0);          compute(smb + STG_SZ);
        CP_WAIT1(); __syncthreads(); issue(7, STG_SZ);     compute(smb + 2 * STG_SZ);
        CP_WAIT1(); __syncthreads();                       compute(smb);
        CP_WAIT0(); __syncthreads();                       compute(smb + STG_SZ);

        const float* sb_ = skip_b + layer * 512;
        const int lm = lid >> 2, ln = lid & 3;
        const bool is_h = (n0 < 256);
#pragma unroll
        for (int mt = 0; mt < 2; mt++) {
            int row0 = m0 + wm * 32 + mt * 16 + lm;
#pragma unroll
            for (int nn = 0; nn < 4; nn++) {
                int oc = n0 + wn * 32 + nn * 8 + 2 * ln;
                float b0 = __ldg(sb_ + oc), b1 = __ldg(sb_ + oc + 1);
#pragma unroll
                for (int u = 0; u < 2; u++) {
                    int row = row0 + u * 8;
                    float v0 = acc[mt][nn][2 * u] + b0;
                    float v1 = acc[mt][nn][2 * u + 1] + b1;
                    if (is_h) {
                        float2* hp = (float2*)(g_h + (size_t)row * DH + oc);
                        float2 cur = *hp;
                        float nh0 = cur.x + v0, nh1 = cur.y + v1;
                        *hp = make_float2(nh0, nh1);
                        __nv_bfloat16 a0 = __float2bfloat16(nh0);
                        __nv_bfloat16 a1 = __float2bfloat16(nh1);
                        *(__nv_bfloat162*)(g_hhi + (size_t)row * DH + oc) = __nv_bfloat162(a0, a1);
                        *(__nv_bfloat162*)(g_hlo + (size_t)row * DH + oc) = __nv_bfloat162(
                            __float2bfloat16(nh0 - __bfloat162float(a0)),
                            __float2bfloat16(nh1 - __bfloat162float(a1)));
                    } else {
                        float2* sp = (float2*)(g_skip + (size_t)row * DH + (oc - 256));
                        float2 prev = (layer == 0) ? make_float2(0.f, 0.f) : *sp;
                        *sp = make_float2(prev.x + v0, prev.y + v1);
                    }
                }
            }
        }
        __syncthreads();
        if (tid == 0) red_rel_add(&g_sdone[(layer * B_SZ + bb) * 8 + ttile]);
    }
}

// ---------------- launch -----------------------------------------------------
extern "C" void kernel_launch(void* const* d_in, const int* in_sizes, int n_in,
                              void* d_out, int out_size) {
    const float* X_cov   = (const float*)d_in[1];
    const float* X_lag   = (const float*)d_in[2];
    const float* y       = (const float*)d_in[3];
    const float* up_w    = (const float*)d_in[5];
    const float* up_b    = (const float*)d_in[6];
    const float* conv_w  = (const float*)d_in[7];
    const float* conv_b  = (const float*)d_in[8];
    const float* skip_w  = (const float*)d_in[9];
    const float* skip_b  = (const float*)d_in[10];
    const float* fc_w    = (const float*)d_in[11];
    const float* fc_b    = (const float*)d_in[12];
    const float* loc_w   = (const float*)d_in[13];
    const float* loc_b   = (const float*)d_in[14];
    const float* scale_w = (const float*)d_in[15];
    const float* scale_b = (const float*)d_in[16];
    float* out = (float*)d_out;

    cudaFuncSetAttribute(mega, cudaFuncAttributeMaxDynamicSharedMemorySize, SMEM_DYN);

    init_k<<<(NL * B_SZ * 8 + 255) / 256, 256>>>();
    mega<<<MEGA_BLOCKS, 256, SMEM_DYN>>>(conv_w, skip_w, X_lag, X_cov,
                                         up_w, up_b, conv_b, skip_b,
                                         y, fc_w, fc_b, loc_w, loc_b,
                                         scale_w, scale_b, out);
}

// round 17
// speedup vs baseline: 1.7049x; 1.0023x over previous
#include <cuda_runtime.h>
#include <cuda_bf16.h>
#include <cstdint>
#include <math.h>

#define T_LEN 1024
#define B_SZ  64
#define DH    256
#define NL    8
#define OUTL  24
#define M_TOT (B_SZ * T_LEN)
#define UP_T0_TILE 2              // up computed for t-tiles 2..7

// ---------------- device scratch -------------------------------------------
__device__ __align__(128) float          g_h   [M_TOT * DH];
__device__ __align__(128) float          g_skip[M_TOT * DH];
__device__ __align__(128) __nv_bfloat16  g_hhi [M_TOT * DH];
__device__ __align__(128) __nv_bfloat16  g_hlo [M_TOT * DH];
__device__ __align__(128) __nv_bfloat16  g_ghi [M_TOT * DH];
__device__ __align__(128) __nv_bfloat16  g_glo [M_TOT * DH];
__device__ __align__(128) __nv_bfloat16  g_Wc_hi[NL * 3 * 512 * DH];
__device__ __align__(128) __nv_bfloat16  g_Wc_lo[NL * 3 * 512 * DH];
__device__ __align__(128) __nv_bfloat16  g_Ws_hi[NL * 512 * DH];
__device__ __align__(128) __nv_bfloat16  g_Ws_lo[NL * 512 * DH];
__device__ float g_loss;
// dependency flags
__device__ int g_cdone[NL * B_SZ * 8];
__device__ int g_sdone[NL * B_SZ * 8];
__device__ int g_udone[B_SZ * 8];
__device__ int g_wc[NL];
__device__ int g_ws[NL];
__device__ int g_fdone;

// layer-major schedule, L7 skip h-half dropped
__constant__ int c_ts[NL]    = {3, 3, 3, 4, 4, 4, 5, 7};
__constant__ int c_convn[NL] = {2560, 2560, 2560, 2048, 2048, 2048, 1536, 512};
__constant__ int c_skipn[NL] = {1536, 1536, 1536, 1280, 1280, 1280, 1024, 256};
// front: conv-w prep 8*192, skip-w prep 8*64, up 64*6
#define N_PREP_C 1536
#define N_PREP_S 512
#define N_UP     384
#define FRONT    (N_PREP_C + N_PREP_S + N_UP)   // 2432
#define N_GEMM_CONV 15872
#define N_GEMM_SKIP 9728
#define N_GEMM   (N_GEMM_CONV + N_GEMM_SKIP)     // 25600
#define N_FINAL  (OUTL * B_SZ)                   // 1536
#define MEGA_BLOCKS (FRONT + N_GEMM + N_FINAL + 1)  // 29569

// ---------------- PTX helpers ------------------------------------------------
__device__ __forceinline__ uint32_t cvta_s(const void* p) {
    uint32_t a;
    asm("{ .reg .u64 t; cvta.to.shared.u64 t, %1; cvt.u32.u64 %0, t; }" : "=r"(a) : "l"(p));
    return a;
}
__device__ __forceinline__ void ldsm4(uint32_t (&r)[4], uint32_t addr) {
    asm volatile("ldmatrix.sync.aligned.m8n8.x4.shared.b16 {%0,%1,%2,%3}, [%4];"
                 : "=r"(r[0]), "=r"(r[1]), "=r"(r[2]), "=r"(r[3]) : "r"(addr));
}
__device__ __forceinline__ void mma16816(float (&c)[4], const uint32_t (&a)[4],
                                         uint32_t b0, uint32_t b1) {
    asm volatile(
        "mma.sync.aligned.m16n8k16.row.col.f32.bf16.bf16.f32 "
        "{%0,%1,%2,%3}, {%4,%5,%6,%7}, {%8,%9}, {%0,%1,%2,%3};"
        : "+f"(c[0]), "+f"(c[1]), "+f"(c[2]), "+f"(c[3])
        : "r"(a[0]), "r"(a[1]), "r"(a[2]), "r"(a[3]), "r"(b0), "r"(b1));
}
__device__ __forceinline__ void cp16(uint32_t saddr, const void* g, bool pred) {
    int sz = pred ? 16 : 0;
    asm volatile("cp.async.cg.shared.global [%0], [%1], 16, %2;"
                 :: "r"(saddr), "l"(g), "r"(sz) : "memory");
}
#define CP_COMMIT() asm volatile("cp.async.commit_group;" ::: "memory")
#define CP_WAIT1()  asm volatile("cp.async.wait_group 1;" ::: "memory")
#define CP_WAIT0()  asm volatile("cp.async.wait_group 0;" ::: "memory")

__device__ __forceinline__ int ld_acq(const int* p) {
    int v;
    asm volatile("ld.acquire.gpu.global.b32 %0, [%1];" : "=r"(v) : "l"(p) : "memory");
    return v;
}
__device__ __forceinline__ void red_rel_add(int* p) {
    asm volatile("red.release.gpu.global.add.s32 [%0], 1;" :: "l"(p) : "memory");
}
__device__ __forceinline__ void spin_ge(const int* p, int tgt) {
    while (ld_acq(p) < tgt) __nanosleep(64);
}
__device__ __forceinline__ float warp_sum(float v) {
#pragma unroll
    for (int s = 16; s > 0; s >>= 1)
        v += __shfl_xor_sync(0xffffffffu, v, s);
    return v;
}

// Stage: superplane A @0 (128 rows x 128B = [hi|lo]), B @16KB (64 rows x 128B).
#define SP_B  16384
#define STG_SZ 24576
#define SMEM_DYN (3 * STG_SZ)
#define SWA(r, c) ((uint32_t)((r) * 128 + (((c) ^ ((r) & 7)) << 4)))

// ---------------- init: zero flags ------------------------------------------
__global__ void init_k() {
    int idx = blockIdx.x * blockDim.x + threadIdx.x;
    if (idx == 0) { g_loss = 0.0f; g_fdone = 0; }
    if (idx < NL * B_SZ * 8) { g_cdone[idx] = 0; g_sdone[idx] = 0; }
    if (idx < B_SZ * 8) g_udone[idx] = 0;
    if (idx < NL) { g_wc[idx] = 0; g_ws[idx] = 0; }
}

// ---------------- mega kernel ------------------------------------------------
__global__ __launch_bounds__(256, 3) void mega(
    const float* __restrict__ conv_w, const float* __restrict__ skip_w,
    const float* __restrict__ X_lag,  const float* __restrict__ X_cov,
    const float* __restrict__ up_w,   const float* __restrict__ up_b,
    const float* __restrict__ conv_b, const float* __restrict__ skip_b,
    const float* __restrict__ y,
    const float* __restrict__ fc_w,   const float* __restrict__ fc_b,
    const float* __restrict__ loc_w,  const float* __restrict__ loc_b,
    const float* __restrict__ scale_w, const float* __restrict__ scale_b,
    float* __restrict__ out) {
    extern __shared__ __align__(16) unsigned char sm[];
    const int tid = threadIdx.x;
    int id = blockIdx.x;

    // ===== front section: weight prep + up projection =====
    if (id < N_PREP_C) {
        int layer = id / 192;
        int base = (id % 192) * 2048;
#pragma unroll
        for (int e = 0; e < 8; e++) {
            int loc = base + tid * 8 + e;
            int ic = loc & 255;
            int np = (loc >> 8) & 511;
            int tap = loc >> 17;
            int c = np >> 1, s = np & 1;
            int oc = c + s * 256;
            size_t gidx = (size_t)layer * (3 * 512 * 256) + loc;
            float v = conv_w[((size_t)(layer * 512 + oc) * DH + ic) * 3 + tap];
            __nv_bfloat16 hi = __float2bfloat16(v);
            g_Wc_hi[gidx] = hi;
            g_Wc_lo[gidx] = __float2bfloat16(v - __bfloat162float(hi));
        }
        __syncthreads();
        if (tid == 0) red_rel_add(&g_wc[layer]);
        return;
    }
    if (id < N_PREP_C + N_PREP_S) {
        id -= N_PREP_C;
        int layer = id / 64;
        int base = (id % 64) * 2048;
#pragma unroll
        for (int e = 0; e < 8; e++) {
            int loc = base + tid * 8 + e;
            size_t gidx = (size_t)layer * (512 * 256) + loc;
            float v = skip_w[gidx];
            __nv_bfloat16 hi = __float2bfloat16(v);
            g_Ws_hi[gidx] = hi;
            g_Ws_lo[gidx] = __float2bfloat16(v - __bfloat162float(hi));
        }
        __syncthreads();
        if (tid == 0) red_rel_add(&g_ws[layer]);
        return;
    }
    if (id < FRONT) {
        id -= N_PREP_C + N_PREP_S;
        int bidx = id / 6;
        int ttile = UP_T0_TILE + id % 6;
        int t0 = ttile * 128;
        float* xs = (float*)sm;   // [128][16]
#pragma unroll
        for (int i = 0; i < 8; i++) {
            int e = tid + i * 256;
            int r = e >> 4, j = e & 15;
            int t = t0 + r;
            xs[e] = (j < 8) ? X_lag[((size_t)t * B_SZ + bidx) * 8 + j]
                            : X_cov[((size_t)t * B_SZ + bidx) * 8 + (j - 8)];
        }
        __syncthreads();
        int c = tid;
        float w[16];
#pragma unroll
        for (int j = 0; j < 16; j++) w[j] = up_w[j * DH + c];
        float bb = up_b[c];
        for (int r = 0; r < 128; r++) {
            float acc = bb;
            const float* xr = xs + r * 16;
#pragma unroll
            for (int j = 0; j < 16; j++) acc += xr[j] * w[j];
            size_t o = ((size_t)bidx * T_LEN + t0 + r) * DH + c;
            g_h[o] = acc;
            __nv_bfloat16 hi = __float2bfloat16(acc);
            g_hhi[o] = hi;
            g_hlo[o] = __float2bfloat16(acc - __bfloat162float(hi));
        }
        __syncthreads();
        if (tid == 0) red_rel_add(&g_udone[bidx * 8 + ttile]);
        return;
    }

    // ===== tail section: FC head + Gaussian NLL + finish =====
    if (id >= FRONT + N_GEMM) {
        int row = id - (FRONT + N_GEMM);
        if (row == N_FINAL) {
            if (tid == 0) {
                spin_ge(&g_fdone, N_FINAL);
                float L = -g_loss / (float)(OUTL * B_SZ);
                out[0] = L;
                out[1] = L;
            }
            return;
        }
        int tt = row >> 6;
        int b = row & 63;
        int t = T_LEN - OUTL + tt;
        size_t r = (size_t)b * T_LEN + t;
        if (tid == 0) spin_ge(&g_sdone[(7 * B_SZ + b) * 8 + 7], 4);
        __syncthreads();
        float* srow = (float*)sm;           // [256]
        float* red  = (float*)sm + 256;     // [16]
        int c = tid;
        srow[c] = g_skip[r * DH + c];
        __syncthreads();
        float acc = fc_b[c];
#pragma unroll 8
        for (int k = 0; k < DH; k++) acc += srow[k] * fc_w[k * DH + c];
        float ff = fmaxf(acc, 0.0f);

        // warp-shuffle partial sums for loc and scale dots
        float pl = warp_sum(ff * loc_w[c]);
        float ps = warp_sum(ff * scale_w[c]);
        int wid = tid >> 5, lid = tid & 31;
        if (lid == 0) { red[wid] = pl; red[8 + wid] = ps; }
        __syncthreads();
        if (tid == 0) {
            float loc = loc_b[0], sraw = scale_b[0];
#pragma unroll
            for (int wq = 0; wq < 8; wq++) { loc += red[wq]; sraw += red[8 + wq]; }
            float sp = (sraw > 20.0f) ? sraw : log1pf(expf(sraw));
            float scale = sp + 1e-6f;
            float yt = y[(size_t)t * B_SZ + b];
            float z = (yt - loc) / scale;
            float lp = -0.5f * z * z - logf(scale) - 0.91893853320467274f;
            out[2 + row] = loc;
            out[2 + OUTL * B_SZ + row] = scale;
            atomicAdd(&g_loss, lp);
            red_rel_add(&g_fdone);
        }
        return;
    }

    // ===== GEMM section: layer-major =====
    int rem = id - FRONT;
    int layer = 0;
    while (layer < NL - 1 && rem >= c_convn[layer] + c_skipn[layer]) {
        rem -= c_convn[layer] + c_skipn[layer];
        layer++;
    }
    const int tstart = c_ts[layer];
    const int nt = 8 - tstart;
    const bool isconv = rem < c_convn[layer];

    const int wid = tid >> 5, lid = tid & 31;
    const int wm = wid & 3, wn = wid >> 2;          // warp tile 32x32
    const uint32_t smb = cvta_s(sm);
    const int lrow = lid & 15, khalf = lid >> 4;
    const int lc = tid & 3, lislo = (tid >> 2) & 1, lrr = tid >> 3;
    const int chunk = lislo * 4 + lc;

    float acc[2][4][4];
#pragma unroll
    for (int a = 0; a < 2; a++)
#pragma unroll
        for (int b = 0; b < 4; b++)
#pragma unroll
            for (int d = 0; d < 4; d++) acc[a][b][d] = 0.0f;

    if (isconv) {
        const int nx = rem & 7;
        const int y2 = rem >> 3;
        const int bidx = y2 / nt;
        const int ttile = tstart + y2 % nt;
        const int n0 = nx * 64;
        const int m0 = bidx * T_LEN + ttile * 128;
        const int t0 = ttile * 128;
        const int dil = 1 << layer;

        if (tid == 0) {
            spin_ge(&g_wc[layer], 192);
            if (layer == 0) {
                spin_ge(&g_udone[bidx * 8 + ttile], 1);
                spin_ge(&g_udone[bidx * 8 + ttile - 1], 1);
            } else {
                int lo = ttile - 2, tsp = c_ts[layer - 1];
                if (lo < tsp) lo = tsp;
                for (int tp = lo; tp <= ttile; tp++) {
                    int tgt = (tp == 7) ? 8 : 4;
                    spin_ge(&g_sdone[((layer - 1) * B_SZ + bidx) * 8 + tp], tgt);
                }
            }
        }
        __syncthreads();

        auto issue = [&](int it, uint32_t stgoff) {
            int tap = it >> 3, kc = it & 7;
            int kk = kc * 32;
            int off = (2 - tap) * dil;
            const __nv_bfloat16* Asrc = (lislo ? g_hlo : g_hhi)
                                      + ((long)(m0 - off) * DH + kk) + lc * 8;
            const __nv_bfloat16* Bsrc = (lislo ? g_Wc_lo : g_Wc_hi)
                                      + ((size_t)(layer * 3 + tap) * 512 + n0) * DH + kk + lc * 8;
            uint32_t sb = smb + stgoff;
#pragma unroll
            for (int q = 0; q < 4; q++) {
                int r = q * 32 + lrr;
                cp16(sb + SWA(r, chunk), Asrc + (size_t)r * DH, (t0 + r) >= off);
            }
#pragma unroll
            for (int q = 0; q < 2; q++) {
                int r = q * 32 + lrr;
                cp16(sb + SP_B + SWA(r, chunk), Bsrc + (size_t)r * DH, true);
            }
            CP_COMMIT();
        };
        auto compute = [&](uint32_t s0) {
#pragma unroll
            for (int ks = 0; ks < 2; ks++) {
                int ch = 2 * ks + khalf;
                uint32_t a[2][4], bH[2][4], bL[2][4];
#pragma unroll
                for (int q = 0; q < 2; q++) {
                    int rB = wn * 32 + q * 16 + lrow;
                    ldsm4(bH[q], s0 + SP_B + SWA(rB, ch));
                    ldsm4(bL[q], s0 + SP_B + SWA(rB, ch + 4));
                }
#pragma unroll
                for (int mt = 0; mt < 2; mt++)
                    ldsm4(a[mt], s0 + SWA(wm * 32 + mt * 16 + lrow, ch));
#pragma unroll
                for (int mt = 0; mt < 2; mt++)
#pragma unroll
                    for (int nn = 0; nn < 4; nn++) {
                        int q = nn >> 1, h = nn & 1;
                        mma16816(acc[mt][nn], a[mt], bH[q][h], bH[q][h + 2]);
                        mma16816(acc[mt][nn], a[mt], bL[q][h], bL[q][h + 2]);
                    }
#pragma unroll
                for (int mt = 0; mt < 2; mt++)
                    ldsm4(a[mt], s0 + SWA(wm * 32 + mt * 16 + lrow, ch + 4));
#pragma unroll
                for (int mt = 0; mt < 2; mt++)
#pragma unroll
                    for (int nn = 0; nn < 4; nn++) {
                        int q = nn >> 1, h = nn & 1;
                        mma16816(acc[mt][nn], a[mt], bH[q][h], bH[q][h + 2]);
                    }
            }
        };

        issue(0, 0);
        issue(1, STG_SZ);
        for (int mj = 0; mj < 7; mj++) {
            CP_WAIT1(); __syncthreads(); issue(mj * 3 + 2, 2 * STG_SZ); compute(smb);
            CP_WAIT1(); __syncthreads(); issue(mj * 3 + 3, 0);          compute(smb + STG_SZ);
            CP_WAIT1(); __syncthreads(); issue(mj * 3 + 4, STG_SZ);     compute(smb + 2 * STG_SZ);
        }
        CP_WAIT1(); __syncthreads(); issue(23, 2 * STG_SZ); compute(smb);
        CP_WAIT1(); __syncthreads();                         compute(smb + STG_SZ);
        CP_WAIT0(); __syncthreads();                         compute(smb + 2 * STG_SZ);

        const float* cbf = conv_b + layer * 512;
        const int lm = lid >> 2, ln = lid & 3;
#pragma unroll
        for (int mt = 0; mt < 2; mt++) {
            int row0 = m0 + wm * 32 + mt * 16 + lm;
#pragma unroll
            for (int nn = 0; nn < 4; nn++) {
                int ch = ((n0 + wn * 32 + nn * 8) >> 1) + ln;
                float fb = __ldg(cbf + ch), gb = __ldg(cbf + 256 + ch);
#pragma unroll
                for (int u = 0; u < 2; u++) {
                    int row = row0 + u * 8;
                    float f = acc[mt][nn][2 * u] + fb;
                    float g = acc[mt][nn][2 * u + 1] + gb;
                    float e2f = __expf(2.0f * f);
                    float th = (e2f - 1.0f) / (e2f + 1.0f);
                    float val = th / (1.0f + __expf(-g));
                    __nv_bfloat16 hi = __float2bfloat16(val);
                    g_ghi[(size_t)row * DH + ch] = hi;
                    g_glo[(size_t)row * DH + ch] = __float2bfloat16(val - __bfloat162float(hi));
                }
            }
        }
        __syncthreads();
        if (tid == 0) red_rel_add(&g_cdone[(layer * B_SZ + bidx) * 8 + ttile]);
    } else {
        int s = rem - c_convn[layer];
        const int x = s & 3;
        int jj, bb;
        if (layer == NL - 1) { bb = s >> 2; jj = nt; }          // L7: skip-half only
        else { bb = (s >> 2) / (nt + 1); jj = (s >> 2) % (nt + 1); }
        const int ttile = (jj < nt) ? (tstart + jj) : 7;
        const int n0 = ((jj < nt) ? 0 : 256) + x * 64;
        const int m0 = bb * T_LEN + ttile * 128;

        if (tid == 0) {
            spin_ge(&g_ws[layer], 64);
            int hi_t = ttile + 2;
            if (hi_t > 7) hi_t = 7;
            for (int tp = ttile; tp <= hi_t; tp++)
                spin_ge(&g_cdone[(layer * B_SZ + bb) * 8 + tp], 8);
        }
        __syncthreads();

        const __nv_bfloat16* Asrc = (lislo ? g_glo : g_ghi) + (size_t)m0 * DH + lc * 8;
        const __nv_bfloat16* Bsrc = (lislo ? g_Ws_lo : g_Ws_hi)
                                  + ((size_t)layer * 512 + n0) * DH + lc * 8;

        auto issue = [&](int it, uint32_t stgoff) {
            int kk = it * 32;
            uint32_t sb = smb + stgoff;
#pragma unroll
            for (int q = 0; q < 4; q++) {
                int r = q * 32 + lrr;
                cp16(sb + SWA(r, chunk), Asrc + (size_t)r * DH + kk, true);
            }
#pragma unroll
            for (int q = 0; q < 2; q++) {
                int r = q * 32 + lrr;
                cp16(sb + SP_B + SWA(r, chunk), Bsrc + (size_t)r * DH + kk, true);
            }
            CP_COMMIT();
        };
        auto compute = [&](uint32_t s0) {
#pragma unroll
            for (int ks = 0; ks < 2; ks++) {
                int ch = 2 * ks + khalf;
                uint32_t a[2][4], bH[2][4], bL[2][4];
#pragma unroll
                for (int q = 0; q < 2; q++) {
                    int rB = wn * 32 + q * 16 + lrow;
                    ldsm4(bH[q], s0 + SP_B + SWA(rB, ch));
                    ldsm4(bL[q], s0 + SP_B + SWA(rB, ch + 4));
                }
#pragma unroll
                for (int mt = 0; mt < 2; mt++)
                    ldsm4(a[mt], s0 + SWA(wm * 32 + mt * 16 + lrow, ch));
#pragma unroll
                for (int mt = 0; mt < 2; mt++)
#pragma unroll
                    for (int nn = 0; nn < 4; nn++) {
                        int q = nn >> 1, h = nn & 1;
                        mma16816(acc[mt][nn], a[mt], bH[q][h], bH[q][h + 2]);
                        mma16816(acc[mt][nn], a[mt], bL[q][h], bL[q][h + 2]);
                    }
#pragma unroll
                for (int mt = 0; mt < 2; mt++)
                    ldsm4(a[mt], s0 + SWA(wm * 32 + mt * 16 + lrow, ch + 4));
#pragma unroll
                for (int mt = 0; mt < 2; mt++)
#pragma unroll
                    for (int nn = 0; nn < 4; nn++) {
                        int q = nn >> 1, h = nn & 1;
                        mma16816(acc[mt][nn], a[mt], bH[q][h], bH[q][h + 2]);
                    }
            }
        };

        issue(0, 0);
        issue(1, STG_SZ);
        CP_WAIT1(); __syncthreads(); issue(2, 2 * STG_SZ); compute(smb);
        CP_WAIT1(); __syncthreads(); issue(3, 0);          compute(smb + STG_SZ);
        CP_WAIT1(); __syncthreads(); issue(4, STG_SZ);     compute(smb + 2 * STG_SZ);
        CP_WAIT1(); __syncthreads(); issue(5, 2 * STG_SZ); compute(smb);
        CP_WAIT1(); __syncthreads(); issue(6, 0);          compute(smb + STG_SZ);
        CP_WAIT1(); __syncthreads(); issue(7, STG_SZ);     compute(smb + 2 * STG_SZ);
        CP_WAIT1(); __syncthreads();                       compute(smb);
        CP_WAIT0(); __syncthreads();                       compute(smb + STG_SZ);

        const float* sb_ = skip_b + layer * 512;
        const int lm = lid >> 2, ln = lid & 3;
        const bool is_h = (n0 < 256);
#pragma unroll
        for (int mt = 0; mt < 2; mt++) {
            int row0 = m0 + wm * 32 + mt * 16 + lm;
#pragma unroll
            for (int nn = 0; nn < 4; nn++) {
                int oc = n0 + wn * 32 + nn * 8 + 2 * ln;
                float b0 = __ldg(sb_ + oc), b1 = __ldg(sb_ + oc + 1);
#pragma unroll
                for (int u = 0; u < 2; u++) {
                    int row = row0 + u * 8;
                    float v0 = acc[mt][nn][2 * u] + b0;
                    float v1 = acc[mt][nn][2 * u + 1] + b1;
                    if (is_h) {
                        float2* hp = (float2*)(g_h + (size_t)row * DH + oc);
                        float2 cur = *hp;
                        float nh0 = cur.x + v0, nh1 = cur.y + v1;
                        *hp = make_float2(nh0, nh1);
                        __nv_bfloat16 a0 = __float2bfloat16(nh0);
                        __nv_bfloat16 a1 = __float2bfloat16(nh1);
                        *(__nv_bfloat162*)(g_hhi + (size_t)row * DH + oc) = __nv_bfloat162(a0, a1);
                        *(__nv_bfloat162*)(g_hlo + (size_t)row * DH + oc) = __nv_bfloat162(
                            __float2bfloat16(nh0 - __bfloat162float(a0)),
                            __float2bfloat16(nh1 - __bfloat162float(a1)));
                    } else {
                        float2* sp = (float2*)(g_skip + (size_t)row * DH + (oc - 256));
                        float2 prev = (layer == 0) ? make_float2(0.f, 0.f) : *sp;
                        *sp = make_float2(prev.x + v0, prev.y + v1);
                    }
                }
            }
        }
        __syncthreads();
        if (tid == 0) red_rel_add(&g_sdone[(layer * B_SZ + bb) * 8 + ttile]);
    }
}

// ---------------- launch -----------------------------------------------------
extern "C" void kernel_launch(void* const* d_in, const int* in_sizes, int n_in,
                              void* d_out, int out_size) {
    const float* X_cov   = (const float*)d_in[1];
    const float* X_lag   = (const float*)d_in[2];
    const float* y       = (const float*)d_in[3];
    const float* up_w    = (const float*)d_in[5];
    const float* up_b    = (const float*)d_in[6];
    const float* conv_w  = (const float*)d_in[7];
    const float* conv_b  = (const float*)d_in[8];
    const float* skip_w  = (const float*)d_in[9];
    const float* skip_b  = (const float*)d_in[10];
    const float* fc_w    = (const float*)d_in[11];
    const float* fc_b    = (const float*)d_in[12];
    const float* loc_w   = (const float*)d_in[13];
    const float* loc_b   = (const float*)d_in[14];
    const float* scale_w = (const float*)d_in[15];
    const float* scale_b = (const float*)d_in[16];
    float* out = (float*)d_out;

    cudaFuncSetAttribute(mega, cudaFuncAttributeMaxDynamicSharedMemorySize, SMEM_DYN);

    init_k<<<(NL * B_SZ * 8 + 255) / 256, 256>>>();
    mega<<<MEGA_BLOCKS, 256, SMEM_DYN>>>(conv_w, skip_w, X_lag, X_cov,
                                         up_w, up_b, conv_b, skip_b,
                                         y, fc_w, fc_b, loc_w, loc_b,
                                         scale_w, scale_b, out);
}